// round 13
// baseline (speedup 1.0000x reference)
#include <cuda_runtime.h>
#include <cuda_bf16.h>
#include <math.h>
#include <stdint.h>

typedef unsigned int u32;
typedef __nv_bfloat16 bf16;

#define BB 2
#define SS 2048
#define DD 1024
#define HH 16
#define DKK 64
#define NROWS (BB*SS)
#define OUT_ELEMS ((size_t)BB*SS*DD)
#define P_ELEMS   ((size_t)BB*HH*SS*SS)

// ---------------------------------------------------------------------------
// Device scratch (allocation-free)
// ---------------------------------------------------------------------------
__device__ __align__(16) bf16 g_aq_hi[NROWS*DD], g_aq_lo[NROWS*DD];
__device__ __align__(16) bf16 g_ak_hi[NROWS*DD], g_ak_lo[NROWS*DD];
__device__ __align__(16) bf16 g_av_hi[NROWS*DD], g_av_lo[NROWS*DD];
__device__ __align__(16) bf16 g_wT_hi[4][DD*DD], g_wT_lo[4][DD*DD];
__device__ __align__(16) bf16 g_qh_hi[NROWS*DD], g_qh_lo[NROWS*DD];
__device__ __align__(16) bf16 g_kh_hi[NROWS*DD], g_kh_lo[NROWS*DD];
__device__ __align__(16) bf16 g_vh_hi[NROWS*DD], g_vh_lo[NROWS*DD];
__device__ __align__(16) bf16 g_o_hi[NROWS*DD],  g_o_lo[NROWS*DD];
__device__ float g_mb[BB*SS];

// ---------------------------------------------------------------------------
// PTX helpers
// ---------------------------------------------------------------------------
__device__ __forceinline__ u32 cvta_s(const void* p) {
    return (u32)__cvta_generic_to_shared(p);
}
__device__ __forceinline__ void cp_async16(u32 dst, const void* src) {
    asm volatile("cp.async.cg.shared.global [%0], [%1], 16;\n" :: "r"(dst), "l"(src));
}
__device__ __forceinline__ void cp_commit() {
    asm volatile("cp.async.commit_group;\n" ::: "memory");
}
__device__ __forceinline__ void cp_wait0() {
    asm volatile("cp.async.wait_group 0;\n" ::: "memory");
}
__device__ __forceinline__ void cp_wait1() {
    asm volatile("cp.async.wait_group 1;\n" ::: "memory");
}
__device__ __forceinline__ void ldsm_x4(u32* r, u32 addr) {
    asm volatile("ldmatrix.sync.aligned.m8n8.x4.shared.b16 {%0,%1,%2,%3}, [%4];\n"
        : "=r"(r[0]), "=r"(r[1]), "=r"(r[2]), "=r"(r[3]) : "r"(addr));
}
__device__ __forceinline__ void ldsm_x4_t(u32* r, u32 addr) {
    asm volatile("ldmatrix.sync.aligned.m8n8.x4.trans.shared.b16 {%0,%1,%2,%3}, [%4];\n"
        : "=r"(r[0]), "=r"(r[1]), "=r"(r[2]), "=r"(r[3]) : "r"(addr));
}
__device__ __forceinline__ void mma16816(float* c, u32 a0, u32 a1, u32 a2, u32 a3,
                                         u32 b0, u32 b1)
{
    asm volatile(
        "mma.sync.aligned.m16n8k16.row.col.f32.bf16.bf16.f32 "
        "{%0,%1,%2,%3},{%4,%5,%6,%7},{%8,%9},{%0,%1,%2,%3};\n"
        : "+f"(c[0]), "+f"(c[1]), "+f"(c[2]), "+f"(c[3])
        : "r"(a0), "r"(a1), "r"(a2), "r"(a3), "r"(b0), "r"(b1));
}
__device__ __forceinline__ void f2bf_split(float v, bf16& h, bf16& l) {
    h = __float2bfloat16_rn(v);
    l = __float2bfloat16_rn(v - __bfloat162float(h));
}
__device__ __forceinline__ u32 bf2_pack(bf16 a, bf16 b) {
    __nv_bfloat162 t; t.x = a; t.y = b;
    return *reinterpret_cast<u32*>(&t);
}
__device__ __forceinline__ void split_pack2(float a, float b, u32& hp, u32& lp) {
    bf16 ha, la, hb, lb;
    f2bf_split(a, ha, la);
    f2bf_split(b, hb, lb);
    hp = bf2_pack(ha, hb);
    lp = bf2_pack(la, lb);
}

// Stage [128 rows x 64 bf16] into swizzled smem (128B rows, 16B chunks,
// chunk' = chunk ^ (row&7)).
__device__ __forceinline__ void stage128(u32 sbase, const bf16* g, u32 gstride_bytes, int tid) {
#pragma unroll
    for (int it = 0; it < 4; it++) {
        int idx = it * 256 + tid;
        int r = idx >> 3, c = idx & 7;
        cp_async16(sbase + (u32)(r * 128) + (u32)((c ^ (r & 7)) << 4),
                   (const char*)g + (size_t)r * gstride_bytes + (size_t)c * 16);
    }
}

// Stage [64 rows x 64 bf16] (head-major, 128B contiguous rows)
__device__ __forceinline__ void stage64(u32 sbase, const bf16* g, int tid) {
#pragma unroll
    for (int it = 0; it < 2; it++) {
        int idx = it * 256 + tid;   // 0..511
        int r = idx >> 3, c = idx & 7;
        cp_async16(sbase + (u32)(r * 128) + (u32)((c ^ (r & 7)) << 4),
                   (const char*)g + (size_t)r * 128 + (size_t)c * 16);
    }
}

// ---------------------------------------------------------------------------
// Batched pre-split kernel; y==3 plane converts the mask (dtype sniffing)
// ---------------------------------------------------------------------------
struct SplitBatch {
    const float4* x[3];
    uint2* hi[3];
    uint2* lo[3];
    const unsigned char* mraw;
    float* mb;
};

__global__ void __launch_bounds__(256) split3_kernel(SplitBatch sbt)
{
    int z = blockIdx.y;
    if (z == 3) {
        // mask conversion: only block x==0 does the work (4096 elems)
        if (blockIdx.x != 0) return;
        __shared__ int flag1, flag3;
        int tid = threadIdx.x;
        if (tid == 0) { flag1 = 0; flag3 = 0; }
        __syncthreads();
        const unsigned char* mraw = sbt.mraw;
        for (int i = tid; i < NROWS; i += 256) {
            unsigned char by = mraw[i];
            if (((i & 3) == 1) && by) flag1 = 1;
            if (((i & 3) == 3) && by) flag3 = 1;
        }
        __syncthreads();
        int mode = flag1 ? 0 : (flag3 ? 2 : 1);
        for (int i = tid; i < NROWS; i += 256) {
            bool masked;
            if (mode == 0)      masked = (mraw[i] != 0);
            else if (mode == 1) masked = (((const int*)mraw)[i] != 0);
            else                masked = (((const float*)mraw)[i] != 0.0f);
            sbt.mb[i] = masked ? -1e30f : 0.0f;
        }
        return;
    }
    int idx = blockIdx.x * 256 + threadIdx.x;
    float4 v = sbt.x[z][idx];
    bf16 h0, l0, h1, l1, h2, l2, h3, l3;
    f2bf_split(v.x, h0, l0); f2bf_split(v.y, h1, l1);
    f2bf_split(v.z, h2, l2); f2bf_split(v.w, h3, l3);
    uint2 ho; ho.x = bf2_pack(h0, h1); ho.y = bf2_pack(h2, h3);
    uint2 lu; lu.x = bf2_pack(l0, l1); lu.y = bf2_pack(l2, l3);
    sbt.hi[z][idx] = ho;
    sbt.lo[z][idx] = lu;
}

struct SplitTBatch {
    const float* W[4];
    bf16* hiT[4];
    bf16* loT[4];
};

__global__ void __launch_bounds__(256) splitT4_kernel(SplitTBatch st)
{
    __shared__ float t[32][33];
    int z = blockIdx.z;
    const float* W = st.W[z];
    int bx = blockIdx.x * 32, by = blockIdx.y * 32;
    int tx = threadIdx.x & 31, ty = threadIdx.x >> 5;
#pragma unroll
    for (int j = 0; j < 32; j += 8)
        t[ty + j][tx] = W[(size_t)(by + ty + j) * DD + bx + tx];
    __syncthreads();
#pragma unroll
    for (int j = 0; j < 32; j += 8) {
        float v = t[tx][ty + j];
        bf16 h, l;
        f2bf_split(v, h, l);
        size_t o = (size_t)(bx + ty + j) * DD + by + tx;
        st.hiT[z][o] = h;
        st.loT[z][o] = l;
    }
}

// ---------------------------------------------------------------------------
// Batched tensor-core GEMM (bf16x3), 3-stage cp.async pipeline — R9/R12 version
// ---------------------------------------------------------------------------
#define TG_SMEM (3*65536)

struct GemmBatch {
    const bf16* Ah[3]; const bf16* Al[3];
    const bf16* Bh[3]; const bf16* Bl[3];
    const float* bias[3];
    bf16* oh[3]; bf16* ol[3];
    float* outF[3];
    float esc[3];
    int headMode;
};

__global__ void __launch_bounds__(256) tgemm_kernel(GemmBatch gb)
{
    extern __shared__ char smc[];
    u32 sb = cvta_s(smc);

    int z = blockIdx.z;
    int tid = threadIdx.x;
    int lane = tid & 31, wid = tid >> 5;
    int g = lane >> 2, tg = lane & 3;
    int i8 = lane & 7, sel = lane >> 3;
    int m0 = blockIdx.y * 128, n0 = blockIdx.x * 128;
    int wm = (wid & 1) * 64, wn = (wid >> 1) * 32;

    const size_t K = DD;
    const bf16* pAh = gb.Ah[z] + (size_t)m0 * K;
    const bf16* pAl = gb.Al[z] + (size_t)m0 * K;
    const bf16* pBh = gb.Bh[z] + (size_t)n0 * K;
    const bf16* pBl = gb.Bl[z] + (size_t)n0 * K;

    float acc[4][4][4];
#pragma unroll
    for (int mt = 0; mt < 4; mt++)
#pragma unroll
        for (int nt = 0; nt < 4; nt++)
#pragma unroll
            for (int i = 0; i < 4; i++) acc[mt][nt][i] = 0.0f;

#pragma unroll
    for (int s = 0; s < 2; s++) {
        u32 ss = sb + (u32)(s * 65536);
        stage128(ss +     0, pAh + s * 64, 2048, tid);
        stage128(ss + 16384, pAl + s * 64, 2048, tid);
        stage128(ss + 32768, pBh + s * 64, 2048, tid);
        stage128(ss + 49152, pBl + s * 64, 2048, tid);
        cp_commit();
    }

    int buf = 0, wbuf = 2;
    for (int kt = 0; kt < 16; kt++) {
        if (kt <= 13) cp_wait1(); else cp_wait0();
        __syncthreads();
        if (kt <= 13) {
            int k1 = (kt + 2) * 64;
            u32 sn = sb + (u32)(wbuf * 65536);
            stage128(sn +     0, pAh + k1, 2048, tid);
            stage128(sn + 16384, pAl + k1, 2048, tid);
            stage128(sn + 32768, pBh + k1, 2048, tid);
            stage128(sn + 49152, pBl + k1, 2048, tid);
            cp_commit();
            wbuf = (wbuf == 2) ? 0 : wbuf + 1;
        }
        u32 st = sb + (u32)(buf * 65536);
        buf = (buf == 2) ? 0 : buf + 1;

#pragma unroll
        for (int ks4 = 0; ks4 < 4; ks4++) {
            int ks = ks4 * 16;
            u32 ah[4][4], al[4][4];
#pragma unroll
            for (int mt = 0; mt < 4; mt++) {
                int arow = wm + mt * 16 + i8 + ((sel & 1) << 3);
                u32 aoff = (u32)(arow * 128) + ((u32)((((ks >> 3) + (sel >> 1)) ^ i8)) << 4);
                ldsm_x4(ah[mt], st + aoff);
                ldsm_x4(al[mt], st + 16384 + aoff);
            }
#pragma unroll
            for (int ntp = 0; ntp < 2; ntp++) {
                int brow = wn + ntp * 16 + i8 + ((sel >> 1) << 3);
                u32 boff = (u32)(brow * 128) + ((u32)((((ks >> 3) + (sel & 1)) ^ i8)) << 4);
                u32 bh[4], bl[4];
                ldsm_x4(bh, st + 32768 + boff);
                ldsm_x4(bl, st + 49152 + boff);
#pragma unroll
                for (int mt = 0; mt < 4; mt++)
                    mma16816(acc[mt][2*ntp],   ah[mt][0], ah[mt][1], ah[mt][2], ah[mt][3], bh[0], bh[1]);
#pragma unroll
                for (int mt = 0; mt < 4; mt++)
                    mma16816(acc[mt][2*ntp+1], ah[mt][0], ah[mt][1], ah[mt][2], ah[mt][3], bh[2], bh[3]);
#pragma unroll
                for (int mt = 0; mt < 4; mt++)
                    mma16816(acc[mt][2*ntp],   ah[mt][0], ah[mt][1], ah[mt][2], ah[mt][3], bl[0], bl[1]);
#pragma unroll
                for (int mt = 0; mt < 4; mt++)
                    mma16816(acc[mt][2*ntp+1], ah[mt][0], ah[mt][1], ah[mt][2], ah[mt][3], bl[2], bl[3]);
#pragma unroll
                for (int mt = 0; mt < 4; mt++)
                    mma16816(acc[mt][2*ntp],   al[mt][0], al[mt][1], al[mt][2], al[mt][3], bh[0], bh[1]);
#pragma unroll
                for (int mt = 0; mt < 4; mt++)
                    mma16816(acc[mt][2*ntp+1], al[mt][0], al[mt][1], al[mt][2], al[mt][3], bh[2], bh[3]);
            }
        }
    }

    const float* bias = gb.bias[z];
    float escale = gb.esc[z];
#pragma unroll
    for (int mt = 0; mt < 4; mt++) {
        int r0 = m0 + wm + mt * 16 + g;
        int r1 = r0 + 8;
#pragma unroll
        for (int nt = 0; nt < 4; nt++) {
            int c = n0 + wn + nt * 8 + tg * 2;
            float b0 = bias[c], b1 = bias[c + 1];
            float v00 = (acc[mt][nt][0] + b0) * escale;
            float v01 = (acc[mt][nt][1] + b1) * escale;
            float v10 = (acc[mt][nt][2] + b0) * escale;
            float v11 = (acc[mt][nt][3] + b1) * escale;
            if (gb.headMode) {
                int h  = c >> 6;
                int dk = c & 63;
                int b_0 = r0 >> 11, s_0 = r0 & (SS - 1);
                int b_1 = r1 >> 11, s_1 = r1 & (SS - 1);
                size_t o0 = (((size_t)(b_0 * HH + h)) * SS + s_0) * DKK + dk;
                size_t o1 = (((size_t)(b_1 * HH + h)) * SS + s_1) * DKK + dk;
                bf16 h00, l00, h01, l01, h10, l10, h11, l11;
                f2bf_split(v00, h00, l00); f2bf_split(v01, h01, l01);
                f2bf_split(v10, h10, l10); f2bf_split(v11, h11, l11);
                *(u32*)&gb.oh[z][o0] = bf2_pack(h00, h01);
                *(u32*)&gb.ol[z][o0] = bf2_pack(l00, l01);
                *(u32*)&gb.oh[z][o1] = bf2_pack(h10, h11);
                *(u32*)&gb.ol[z][o1] = bf2_pack(l10, l11);
            } else {
                float2 w0; w0.x = v00; w0.y = v01;
                float2 w1; w1.x = v10; w1.y = v11;
                *(float2*)&gb.outF[z][(size_t)r0 * DD + c] = w0;
                *(float2*)&gb.outF[z][(size_t)r1 * DD + c] = w1;
            }
        }
    }
}

// ---------------------------------------------------------------------------
// Attention (two-pass, 2 CTAs/SM):
//  pass 1: 128-key chunks, K-hi only, Q hi-fragments hoisted
//  pass 2: 64-key chunks, K+V hi/lo, streaming hints on p stores / bias loads
// ---------------------------------------------------------------------------
#define ATT_SMEM (32768 + 2*32768)   // 98304 -> 2 CTAs/SM

__global__ void __launch_bounds__(256, 2) attn_kernel(
    const bf16* __restrict__ qh_hi, const bf16* __restrict__ qh_lo,
    const bf16* __restrict__ kh_hi, const bf16* __restrict__ kh_lo,
    const bf16* __restrict__ vh_hi, const bf16* __restrict__ vh_lo,
    const float* __restrict__ attn_bias, const float* __restrict__ maskbias,
    float* __restrict__ p_out,
    bf16* __restrict__ o_hi, bf16* __restrict__ o_lo)
{
    extern __shared__ char smc[];
    u32 sb = cvta_s(smc);
    u32 sQh = sb;
    u32 sQl = sb + 16384;

    int tid = threadIdx.x;
    int lane = tid & 31, wid = tid >> 5;
    int g = lane >> 2, tg = lane & 3;
    int i8 = lane & 7, sel = lane >> 3;
    int bh = blockIdx.y;
    int b  = bh >> 4;
    int q0 = blockIdx.x * 128;
    int wq = wid * 16;

    const bf16* kb_h = kh_hi + (size_t)bh * SS * DKK;
    const bf16* kb_l = kh_lo + (size_t)bh * SS * DKK;
    const bf16* vb_h = vh_hi + (size_t)bh * SS * DKK;
    const bf16* vb_l = vh_lo + (size_t)bh * SS * DKK;
    const float* mbp = maskbias + b * SS;

    // ---- Q load + pass-1 prologue ----
    stage128(sQh, qh_hi + ((size_t)bh * SS + q0) * DKK, 128, tid);
    stage128(sQl, qh_lo + ((size_t)bh * SS + q0) * DKK, 128, tid);
    stage128(sb + 32768, kb_h, 128, tid);
    cp_commit();
    stage128(sb + 32768 + 16384, kb_h + (size_t)128 * DKK, 128, tid);
    cp_commit();

    float lsum0 = 0.0f, lsum1 = 0.0f;
    int rr0 = q0 + wq + g;

    // =============== PASS 1: lsum (hi-only), 16 chunks of 128 ===============
    {
        // hoist Q hi fragments (chunk-invariant): 16 regs
        u32 qf[4][4];
        {
            // Q staging arrives with the first committed group; wait for all
            cp_wait0();
            __syncthreads();
#pragma unroll
            for (int ks4 = 0; ks4 < 4; ks4++) {
                int ks = ks4 * 16;
                int arow = wq + i8 + ((sel & 1) << 3);
                u32 aoff = (u32)(arow * 128) + ((u32)((((ks >> 3) + (sel >> 1)) ^ i8)) << 4);
                ldsm_x4(qf[ks4], sQh + aoff);
            }
        }

        int buf = 0, wbuf = 2;
        for (int kt = 0; kt < 16; kt++) {
            if (kt > 0) { if (kt <= 13) cp_wait1(); else cp_wait0(); }
            __syncthreads();
            if (kt <= 13) {
                int kb1 = (kt + 2) * 128;
                stage128(sb + 32768 + (u32)(wbuf * 16384),
                         kb_h + (size_t)kb1 * DKK, 128, tid);
                cp_commit();
                wbuf = (wbuf == 2) ? 0 : wbuf + 1;
            }
            u32 st = sb + 32768 + (u32)(buf * 16384);
            buf = (buf == 2) ? 0 : buf + 1;
            int kb = kt * 128;

            float sc[16][4];
#pragma unroll
            for (int nt = 0; nt < 16; nt++)
#pragma unroll
                for (int i = 0; i < 4; i++) sc[nt][i] = 0.0f;

#pragma unroll
            for (int ks4 = 0; ks4 < 4; ks4++) {
                int ks = ks4 * 16;
#pragma unroll
                for (int ntp = 0; ntp < 8; ntp++) {
                    int brow = ntp * 16 + i8 + ((sel >> 1) << 3);
                    u32 boff = (u32)(brow * 128) + ((u32)((((ks >> 3) + (sel & 1)) ^ i8)) << 4);
                    u32 bhr[4];
                    ldsm_x4(bhr, st + boff);
                    mma16816(sc[2*ntp],   qf[ks4][0], qf[ks4][1], qf[ks4][2], qf[ks4][3], bhr[0], bhr[1]);
                    mma16816(sc[2*ntp+1], qf[ks4][0], qf[ks4][1], qf[ks4][2], qf[ks4][3], bhr[2], bhr[3]);
                }
            }

#pragma unroll
            for (int nt = 0; nt < 16; nt++) {
                int j = nt * 8 + tg * 2;
                float2 mb01 = *(const float2*)(mbp + kb + j);
                lsum0 += __expf(sc[nt][0] + mb01.x);
                lsum0 += __expf(sc[nt][1] + mb01.y);
                lsum1 += __expf(sc[nt][2] + mb01.x);
                lsum1 += __expf(sc[nt][3] + mb01.y);
            }
        }
    }
    __syncthreads();

    lsum0 += __shfl_xor_sync(0xffffffffu, lsum0, 1);
    lsum0 += __shfl_xor_sync(0xffffffffu, lsum0, 2);
    lsum1 += __shfl_xor_sync(0xffffffffu, lsum1, 1);
    lsum1 += __shfl_xor_sync(0xffffffffu, lsum1, 2);
    float il0 = 1.0f / lsum0;
    float il1 = 1.0f / lsum1;

    // =============== PASS 2: p write + PV, 32 chunks of 64 ===============
    float oacc[8][4];
#pragma unroll
    for (int nt = 0; nt < 8; nt++)
#pragma unroll
        for (int i = 0; i < 4; i++) oacc[nt][i] = 0.0f;

    const float* biasrow0 = attn_bias + ((size_t)bh * SS + rr0) * SS;
    const float* biasrow1 = biasrow0 + 8 * SS;
    float* prow0 = p_out ? p_out + ((size_t)bh * SS + rr0) * SS : nullptr;
    float* prow1 = prow0 ? prow0 + 8 * SS : nullptr;

    {
        u32 s0 = sb + 32768;
        stage64(s0 +     0, kb_h, tid);
        stage64(s0 +  8192, kb_l, tid);
        stage64(s0 + 16384, vb_h, tid);
        stage64(s0 + 24576, vb_l, tid);
        cp_commit();
    }

    for (int kt = 0; kt < 32; kt++) {
        cp_wait0();
        __syncthreads();
        u32 st = sb + 32768 + (u32)((kt & 1) * 32768);
        if (kt < 31) {
            int kb1 = (kt + 1) * 64;
            u32 sn = sb + 32768 + (u32)(((kt + 1) & 1) * 32768);
            stage64(sn +     0, kb_h + (size_t)kb1 * DKK, tid);
            stage64(sn +  8192, kb_l + (size_t)kb1 * DKK, tid);
            stage64(sn + 16384, vb_h + (size_t)kb1 * DKK, tid);
            stage64(sn + 24576, vb_l + (size_t)kb1 * DKK, tid);
            cp_commit();
        }
        int kb = kt * 64;

        // ---- QK^T (bf16x3), ntp pairs interleaved ----
        float sc[8][4];
#pragma unroll
        for (int nt = 0; nt < 8; nt++)
#pragma unroll
            for (int i = 0; i < 4; i++) sc[nt][i] = 0.0f;

#pragma unroll
        for (int ks4 = 0; ks4 < 4; ks4++) {
            int ks = ks4 * 16;
            int arow = wq + i8 + ((sel & 1) << 3);
            u32 aoff = (u32)(arow * 128) + ((u32)((((ks >> 3) + (sel >> 1)) ^ i8)) << 4);
            u32 qh[4], ql[4];
            ldsm_x4(qh, sQh + aoff);
            ldsm_x4(ql, sQl + aoff);
#pragma unroll
            for (int pr = 0; pr < 2; pr++) {
                int na = pr * 2, nb = pr * 2 + 1;
                int browa = na * 16 + i8 + ((sel >> 1) << 3);
                int browb = nb * 16 + i8 + ((sel >> 1) << 3);
                u32 boffa = (u32)(browa * 128) + ((u32)((((ks >> 3) + (sel & 1)) ^ i8)) << 4);
                u32 boffb = (u32)(browb * 128) + ((u32)((((ks >> 3) + (sel & 1)) ^ i8)) << 4);
                u32 bh0[4], bl0[4], bh1[4], bl1[4];
                ldsm_x4(bh0, st + boffa);
                ldsm_x4(bl0, st + 8192 + boffa);
                ldsm_x4(bh1, st + boffb);
                ldsm_x4(bl1, st + 8192 + boffb);
                mma16816(sc[2*na],   qh[0], qh[1], qh[2], qh[3], bh0[0], bh0[1]);
                mma16816(sc[2*na+1], qh[0], qh[1], qh[2], qh[3], bh0[2], bh0[3]);
                mma16816(sc[2*nb],   qh[0], qh[1], qh[2], qh[3], bh1[0], bh1[1]);
                mma16816(sc[2*nb+1], qh[0], qh[1], qh[2], qh[3], bh1[2], bh1[3]);
                mma16816(sc[2*na],   qh[0], qh[1], qh[2], qh[3], bl0[0], bl0[1]);
                mma16816(sc[2*na+1], qh[0], qh[1], qh[2], qh[3], bl0[2], bl0[3]);
                mma16816(sc[2*nb],   qh[0], qh[1], qh[2], qh[3], bl1[0], bl1[1]);
                mma16816(sc[2*nb+1], qh[0], qh[1], qh[2], qh[3], bl1[2], bl1[3]);
                mma16816(sc[2*na],   ql[0], ql[1], ql[2], ql[3], bh0[0], bh0[1]);
                mma16816(sc[2*na+1], ql[0], ql[1], ql[2], ql[3], bh0[2], bh0[3]);
                mma16816(sc[2*nb],   ql[0], ql[1], ql[2], ql[3], bh1[0], bh1[1]);
                mma16816(sc[2*nb+1], ql[0], ql[1], ql[2], ql[3], bh1[2], bh1[3]);
            }
        }

        // ---- p = exp(s+mb) * il * bias; streaming loads/stores ----
#pragma unroll
        for (int nt = 0; nt < 8; nt++) {
            int j = nt * 8 + tg * 2;
            float2 mb01 = *(const float2*)(mbp + kb + j);
            float e0 = __expf(sc[nt][0] + mb01.x) * il0;
            float e1 = __expf(sc[nt][1] + mb01.y) * il0;
            float e2 = __expf(sc[nt][2] + mb01.x) * il1;
            float e3 = __expf(sc[nt][3] + mb01.y) * il1;
            float2 bi0 = __ldcs((const float2*)(biasrow0 + kb + j));
            float2 bi1 = __ldcs((const float2*)(biasrow1 + kb + j));
            float p0 = e0 * bi0.x, p1 = e1 * bi0.y;
            float p2 = e2 * bi1.x, p3 = e3 * bi1.y;
            if (prow0) {
                float2 w0; w0.x = p0; w0.y = p1;
                float2 w1; w1.x = p2; w1.y = p3;
                __stcs((float2*)(prow0 + kb + j), w0);
                __stcs((float2*)(prow1 + kb + j), w1);
            }
            sc[nt][0] = p0; sc[nt][1] = p1; sc[nt][2] = p2; sc[nt][3] = p3;
        }

        // ---- PV with final p, ntp pairs interleaved ----
#pragma unroll
        for (int s = 0; s < 4; s++) {
            u32 pa[4], pl[4];
            split_pack2(sc[2*s    ][0], sc[2*s    ][1], pa[0], pl[0]);
            split_pack2(sc[2*s    ][2], sc[2*s    ][3], pa[1], pl[1]);
            split_pack2(sc[2*s + 1][0], sc[2*s + 1][1], pa[2], pl[2]);
            split_pack2(sc[2*s + 1][2], sc[2*s + 1][3], pa[3], pl[3]);
            int vrow = s * 16 + i8 + ((sel & 1) << 3);
#pragma unroll
            for (int pr = 0; pr < 2; pr++) {
                int na = pr * 2, nb = pr * 2 + 1;
                u32 voffa = (u32)(vrow * 128) + ((u32)(((na * 2 + (sel >> 1)) ^ i8)) << 4);
                u32 voffb = (u32)(vrow * 128) + ((u32)(((nb * 2 + (sel >> 1)) ^ i8)) << 4);
                u32 vh0[4], vl0[4], vh1[4], vl1[4];
                ldsm_x4_t(vh0, st + 16384 + voffa);
                ldsm_x4_t(vl0, st + 24576 + voffa);
                ldsm_x4_t(vh1, st + 16384 + voffb);
                ldsm_x4_t(vl1, st + 24576 + voffb);
                mma16816(oacc[2*na],   pa[0], pa[1], pa[2], pa[3], vh0[0], vh0[1]);
                mma16816(oacc[2*na+1], pa[0], pa[1], pa[2], pa[3], vh0[2], vh0[3]);
                mma16816(oacc[2*nb],   pa[0], pa[1], pa[2], pa[3], vh1[0], vh1[1]);
                mma16816(oacc[2*nb+1], pa[0], pa[1], pa[2], pa[3], vh1[2], vh1[3]);
                mma16816(oacc[2*na],   pa[0], pa[1], pa[2], pa[3], vl0[0], vl0[1]);
                mma16816(oacc[2*na+1], pa[0], pa[1], pa[2], pa[3], vl0[2], vl0[3]);
                mma16816(oacc[2*nb],   pa[0], pa[1], pa[2], pa[3], vl1[0], vl1[1]);
                mma16816(oacc[2*nb+1], pa[0], pa[1], pa[2], pa[3], vl1[2], vl1[3]);
                mma16816(oacc[2*na],   pl[0], pl[1], pl[2], pl[3], vh0[0], vh0[1]);
                mma16816(oacc[2*na+1], pl[0], pl[1], pl[2], pl[3], vh0[2], vh0[3]);
                mma16816(oacc[2*nb],   pl[0], pl[1], pl[2], pl[3], vh1[0], vh1[1]);
                mma16816(oacc[2*nb+1], pl[0], pl[1], pl[2], pl[3], vh1[2], vh1[3]);
            }
        }
    }

    // ---- O store ----
    int grow0 = b * SS + rr0;
    int grow1 = grow0 + 8;
    int hcol  = (bh & 15) * DKK;
#pragma unroll
    for (int nt = 0; nt < 8; nt++) {
        int c = hcol + nt * 8 + tg * 2;
        bf16 h00, l00, h01, l01, h10, l10, h11, l11;
        f2bf_split(oacc[nt][0], h00, l00); f2bf_split(oacc[nt][1], h01, l01);
        f2bf_split(oacc[nt][2], h10, l10); f2bf_split(oacc[nt][3], h11, l11);
        *(u32*)&o_hi[(size_t)grow0 * DD + c] = bf2_pack(h00, h01);
        *(u32*)&o_lo[(size_t)grow0 * DD + c] = bf2_pack(l00, l01);
        *(u32*)&o_hi[(size_t)grow1 * DD + c] = bf2_pack(h10, h11);
        *(u32*)&o_lo[(size_t)grow1 * DD + c] = bf2_pack(l10, l11);
    }
}

// ---------------------------------------------------------------------------
// Launch (single stream — graph-capture safe)
// ---------------------------------------------------------------------------
extern "C" void kernel_launch(void* const* d_in, const int* in_sizes, int n_in,
                              void* d_out, int out_size)
{
    const float* q    = (const float*)d_in[0];
    const float* k    = (const float*)d_in[1];
    const float* v    = (const float*)d_in[2];
    const unsigned char* mraw = (const unsigned char*)d_in[3];
    const float* bias = (const float*)d_in[4];
    const float* Wq   = (const float*)d_in[5];
    const float* bq   = (const float*)d_in[6];
    const float* Wk   = (const float*)d_in[7];
    const float* bk   = (const float*)d_in[8];
    const float* Wv   = (const float*)d_in[9];
    const float* bv   = (const float*)d_in[10];
    const float* Wo   = (const float*)d_in[11];
    const float* bo   = (const float*)d_in[12];

    float* out = (float*)d_out;
    float* p_out = ((size_t)out_size >= OUT_ELEMS + P_ELEMS) ? out + OUT_ELEMS : nullptr;

    bf16 *aq_hi, *aq_lo, *ak_hi, *ak_lo, *av_hi, *av_lo;
    bf16 *wT_hi, *wT_lo;
    bf16 *qh_hi, *qh_lo, *kh_hi, *kh_lo, *vh_hi, *vh_lo, *o_hi, *o_lo;
    float *mb;
    cudaGetSymbolAddress((void**)&aq_hi, g_aq_hi);
    cudaGetSymbolAddress((void**)&aq_lo, g_aq_lo);
    cudaGetSymbolAddress((void**)&ak_hi, g_ak_hi);
    cudaGetSymbolAddress((void**)&ak_lo, g_ak_lo);
    cudaGetSymbolAddress((void**)&av_hi, g_av_hi);
    cudaGetSymbolAddress((void**)&av_lo, g_av_lo);
    cudaGetSymbolAddress((void**)&wT_hi, g_wT_hi);
    cudaGetSymbolAddress((void**)&wT_lo, g_wT_lo);
    cudaGetSymbolAddress((void**)&qh_hi, g_qh_hi);
    cudaGetSymbolAddress((void**)&qh_lo, g_qh_lo);
    cudaGetSymbolAddress((void**)&kh_hi, g_kh_hi);
    cudaGetSymbolAddress((void**)&kh_lo, g_kh_lo);
    cudaGetSymbolAddress((void**)&vh_hi, g_vh_hi);
    cudaGetSymbolAddress((void**)&vh_lo, g_vh_lo);
    cudaGetSymbolAddress((void**)&o_hi,  g_o_hi);
    cudaGetSymbolAddress((void**)&o_lo,  g_o_lo);
    cudaGetSymbolAddress((void**)&mb,    g_mb);

    static bool attr_set = false;
    if (!attr_set) {
        cudaFuncSetAttribute(attn_kernel,
                             cudaFuncAttributeMaxDynamicSharedMemorySize, ATT_SMEM);
        cudaFuncSetAttribute(tgemm_kernel,
                             cudaFuncAttributeMaxDynamicSharedMemorySize, TG_SMEM);
        attr_set = true;
    }

    SplitBatch sbt;
    sbt.x[0] = (const float4*)q; sbt.hi[0] = (uint2*)aq_hi; sbt.lo[0] = (uint2*)aq_lo;
    sbt.x[1] = (const float4*)k; sbt.hi[1] = (uint2*)ak_hi; sbt.lo[1] = (uint2*)ak_lo;
    sbt.x[2] = (const float4*)v; sbt.hi[2] = (uint2*)av_hi; sbt.lo[2] = (uint2*)av_lo;
    sbt.mraw = mraw;
    sbt.mb = mb;
    dim3 gs(NROWS*DD/4/256, 4);   // y==3: mask plane
    split3_kernel<<<gs, 256>>>(sbt);

    SplitTBatch stb;
    stb.W[0] = Wq; stb.hiT[0] = wT_hi + 0*DD*DD; stb.loT[0] = wT_lo + 0*DD*DD;
    stb.W[1] = Wk; stb.hiT[1] = wT_hi + 1*DD*DD; stb.loT[1] = wT_lo + 1*DD*DD;
    stb.W[2] = Wv; stb.hiT[2] = wT_hi + 2*DD*DD; stb.loT[2] = wT_lo + 2*DD*DD;
    stb.W[3] = Wo; stb.hiT[3] = wT_hi + 3*DD*DD; stb.loT[3] = wT_lo + 3*DD*DD;
    dim3 gt(32, 32, 4);
    splitT4_kernel<<<gt, 256>>>(stb);

    GemmBatch gbp;
    gbp.Ah[0] = aq_hi; gbp.Al[0] = aq_lo;
    gbp.Ah[1] = ak_hi; gbp.Al[1] = ak_lo;
    gbp.Ah[2] = av_hi; gbp.Al[2] = av_lo;
    gbp.Bh[0] = wT_hi + 0*DD*DD; gbp.Bl[0] = wT_lo + 0*DD*DD;
    gbp.Bh[1] = wT_hi + 1*DD*DD; gbp.Bl[1] = wT_lo + 1*DD*DD;
    gbp.Bh[2] = wT_hi + 2*DD*DD; gbp.Bl[2] = wT_lo + 2*DD*DD;
    gbp.bias[0] = bq; gbp.bias[1] = bk; gbp.bias[2] = bv;
    gbp.oh[0] = qh_hi; gbp.ol[0] = qh_lo;
    gbp.oh[1] = kh_hi; gbp.ol[1] = kh_lo;
    gbp.oh[2] = vh_hi; gbp.ol[2] = vh_lo;
    gbp.outF[0] = gbp.outF[1] = gbp.outF[2] = nullptr;
    gbp.esc[0] = 0.125f; gbp.esc[1] = 1.0f; gbp.esc[2] = 1.0f;
    gbp.headMode = 1;
    dim3 gp3(DD / 128, NROWS / 128, 3);
    tgemm_kernel<<<gp3, 256, TG_SMEM>>>(gbp);

    dim3 ga(SS / 128, BB * HH);
    attn_kernel<<<ga, 256, ATT_SMEM>>>(qh_hi, qh_lo, kh_hi, kh_lo, vh_hi, vh_lo,
                                       bias, mb, p_out, o_hi, o_lo);

    GemmBatch gbo;
    gbo.Ah[0] = o_hi; gbo.Al[0] = o_lo;
    gbo.Bh[0] = wT_hi + 3*DD*DD; gbo.Bl[0] = wT_lo + 3*DD*DD;
    gbo.bias[0] = bo;
    gbo.oh[0] = nullptr; gbo.ol[0] = nullptr;
    gbo.outF[0] = out;
    gbo.esc[0] = 1.0f;
    gbo.headMode = 0;
    gbo.Ah[1] = gbo.Ah[2] = o_hi; gbo.Al[1] = gbo.Al[2] = o_lo;
    gbo.Bh[1] = gbo.Bh[2] = gbo.Bh[0]; gbo.Bl[1] = gbo.Bl[2] = gbo.Bl[0];
    gbo.bias[1] = gbo.bias[2] = bo;
    gbo.oh[1] = gbo.oh[2] = nullptr; gbo.ol[1] = gbo.ol[2] = nullptr;
    gbo.outF[1] = gbo.outF[2] = out;
    gbo.esc[1] = gbo.esc[2] = 1.0f;
    dim3 gp1(DD / 128, NROWS / 128, 1);
    tgemm_kernel<<<gp1, 256, TG_SMEM>>>(gbo);
}

// round 14
// speedup vs baseline: 1.0655x; 1.0655x over previous
#include <cuda_runtime.h>
#include <cuda_bf16.h>
#include <math.h>
#include <stdint.h>

typedef unsigned int u32;
typedef __nv_bfloat16 bf16;

#define BB 2
#define SS 2048
#define DD 1024
#define HH 16
#define DKK 64
#define NROWS (BB*SS)
#define OUT_ELEMS ((size_t)BB*SS*DD)
#define P_ELEMS   ((size_t)BB*HH*SS*SS)

// ---------------------------------------------------------------------------
// Device scratch (allocation-free)
// ---------------------------------------------------------------------------
__device__ __align__(16) bf16 g_aq_hi[NROWS*DD], g_aq_lo[NROWS*DD];
__device__ __align__(16) bf16 g_ak_hi[NROWS*DD], g_ak_lo[NROWS*DD];
__device__ __align__(16) bf16 g_av_hi[NROWS*DD], g_av_lo[NROWS*DD];
__device__ __align__(16) bf16 g_wT_hi[4][DD*DD], g_wT_lo[4][DD*DD];
__device__ __align__(16) bf16 g_qh_hi[NROWS*DD], g_qh_lo[NROWS*DD];
__device__ __align__(16) bf16 g_kh_hi[NROWS*DD], g_kh_lo[NROWS*DD];
__device__ __align__(16) bf16 g_vh_hi[NROWS*DD], g_vh_lo[NROWS*DD];
__device__ __align__(16) bf16 g_o_hi[NROWS*DD],  g_o_lo[NROWS*DD];
__device__ float g_mb[BB*SS];

// ---------------------------------------------------------------------------
// PTX helpers
// ---------------------------------------------------------------------------
__device__ __forceinline__ u32 cvta_s(const void* p) {
    return (u32)__cvta_generic_to_shared(p);
}
__device__ __forceinline__ void cp_async16(u32 dst, const void* src) {
    asm volatile("cp.async.cg.shared.global [%0], [%1], 16;\n" :: "r"(dst), "l"(src));
}
__device__ __forceinline__ void cp_commit() {
    asm volatile("cp.async.commit_group;\n" ::: "memory");
}
__device__ __forceinline__ void cp_wait0() {
    asm volatile("cp.async.wait_group 0;\n" ::: "memory");
}
__device__ __forceinline__ void cp_wait1() {
    asm volatile("cp.async.wait_group 1;\n" ::: "memory");
}
__device__ __forceinline__ void ldsm_x4(u32* r, u32 addr) {
    asm volatile("ldmatrix.sync.aligned.m8n8.x4.shared.b16 {%0,%1,%2,%3}, [%4];\n"
        : "=r"(r[0]), "=r"(r[1]), "=r"(r[2]), "=r"(r[3]) : "r"(addr));
}
__device__ __forceinline__ void ldsm_x4_t(u32* r, u32 addr) {
    asm volatile("ldmatrix.sync.aligned.m8n8.x4.trans.shared.b16 {%0,%1,%2,%3}, [%4];\n"
        : "=r"(r[0]), "=r"(r[1]), "=r"(r[2]), "=r"(r[3]) : "r"(addr));
}
__device__ __forceinline__ void mma16816(float* c, u32 a0, u32 a1, u32 a2, u32 a3,
                                         u32 b0, u32 b1)
{
    asm volatile(
        "mma.sync.aligned.m16n8k16.row.col.f32.bf16.bf16.f32 "
        "{%0,%1,%2,%3},{%4,%5,%6,%7},{%8,%9},{%0,%1,%2,%3};\n"
        : "+f"(c[0]), "+f"(c[1]), "+f"(c[2]), "+f"(c[3])
        : "r"(a0), "r"(a1), "r"(a2), "r"(a3), "r"(b0), "r"(b1));
}
__device__ __forceinline__ void f2bf_split(float v, bf16& h, bf16& l) {
    h = __float2bfloat16_rn(v);
    l = __float2bfloat16_rn(v - __bfloat162float(h));
}
__device__ __forceinline__ u32 bf2_pack(bf16 a, bf16 b) {
    __nv_bfloat162 t; t.x = a; t.y = b;
    return *reinterpret_cast<u32*>(&t);
}
__device__ __forceinline__ void split_pack2(float a, float b, u32& hp, u32& lp) {
    bf16 ha, la, hb, lb;
    f2bf_split(a, ha, la);
    f2bf_split(b, hb, lb);
    hp = bf2_pack(ha, hb);
    lp = bf2_pack(la, lb);
}

// Stage [128 rows x 64 bf16] into swizzled smem (128B rows, 16B chunks,
// chunk' = chunk ^ (row&7)).
__device__ __forceinline__ void stage128(u32 sbase, const bf16* g, u32 gstride_bytes, int tid) {
#pragma unroll
    for (int it = 0; it < 4; it++) {
        int idx = it * 256 + tid;
        int r = idx >> 3, c = idx & 7;
        cp_async16(sbase + (u32)(r * 128) + (u32)((c ^ (r & 7)) << 4),
                   (const char*)g + (size_t)r * gstride_bytes + (size_t)c * 16);
    }
}

// Stage [64 rows x 64 bf16] (head-major, 128B contiguous rows)
__device__ __forceinline__ void stage64(u32 sbase, const bf16* g, int tid) {
#pragma unroll
    for (int it = 0; it < 2; it++) {
        int idx = it * 256 + tid;   // 0..511
        int r = idx >> 3, c = idx & 7;
        cp_async16(sbase + (u32)(r * 128) + (u32)((c ^ (r & 7)) << 4),
                   (const char*)g + (size_t)r * 128 + (size_t)c * 16);
    }
}

// ---------------------------------------------------------------------------
// Batched pre-split kernel; y==3 plane converts the mask (dtype sniffing)
// ---------------------------------------------------------------------------
struct SplitBatch {
    const float4* x[3];
    uint2* hi[3];
    uint2* lo[3];
    const unsigned char* mraw;
    float* mb;
};

__global__ void __launch_bounds__(256) split3_kernel(SplitBatch sbt)
{
    int z = blockIdx.y;
    if (z == 3) {
        if (blockIdx.x != 0) return;
        __shared__ int flag1, flag3;
        int tid = threadIdx.x;
        if (tid == 0) { flag1 = 0; flag3 = 0; }
        __syncthreads();
        const unsigned char* mraw = sbt.mraw;
        for (int i = tid; i < NROWS; i += 256) {
            unsigned char by = mraw[i];
            if (((i & 3) == 1) && by) flag1 = 1;
            if (((i & 3) == 3) && by) flag3 = 1;
        }
        __syncthreads();
        int mode = flag1 ? 0 : (flag3 ? 2 : 1);
        for (int i = tid; i < NROWS; i += 256) {
            bool masked;
            if (mode == 0)      masked = (mraw[i] != 0);
            else if (mode == 1) masked = (((const int*)mraw)[i] != 0);
            else                masked = (((const float*)mraw)[i] != 0.0f);
            sbt.mb[i] = masked ? -1e30f : 0.0f;
        }
        return;
    }
    int idx = blockIdx.x * 256 + threadIdx.x;
    float4 v = sbt.x[z][idx];
    bf16 h0, l0, h1, l1, h2, l2, h3, l3;
    f2bf_split(v.x, h0, l0); f2bf_split(v.y, h1, l1);
    f2bf_split(v.z, h2, l2); f2bf_split(v.w, h3, l3);
    uint2 ho; ho.x = bf2_pack(h0, h1); ho.y = bf2_pack(h2, h3);
    uint2 lu; lu.x = bf2_pack(l0, l1); lu.y = bf2_pack(l2, l3);
    sbt.hi[z][idx] = ho;
    sbt.lo[z][idx] = lu;
}

struct SplitTBatch {
    const float* W[4];
    bf16* hiT[4];
    bf16* loT[4];
};

__global__ void __launch_bounds__(256) splitT4_kernel(SplitTBatch st)
{
    __shared__ float t[32][33];
    int z = blockIdx.z;
    const float* W = st.W[z];
    int bx = blockIdx.x * 32, by = blockIdx.y * 32;
    int tx = threadIdx.x & 31, ty = threadIdx.x >> 5;
#pragma unroll
    for (int j = 0; j < 32; j += 8)
        t[ty + j][tx] = W[(size_t)(by + ty + j) * DD + bx + tx];
    __syncthreads();
#pragma unroll
    for (int j = 0; j < 32; j += 8) {
        float v = t[tx][ty + j];
        bf16 h, l;
        f2bf_split(v, h, l);
        size_t o = (size_t)(bx + ty + j) * DD + by + tx;
        st.hiT[z][o] = h;
        st.loT[z][o] = l;
    }
}

// ---------------------------------------------------------------------------
// Batched tensor-core GEMM (bf16x3), 3-stage cp.async pipeline — R9/R12 version
// ---------------------------------------------------------------------------
#define TG_SMEM (3*65536)

struct GemmBatch {
    const bf16* Ah[3]; const bf16* Al[3];
    const bf16* Bh[3]; const bf16* Bl[3];
    const float* bias[3];
    bf16* oh[3]; bf16* ol[3];
    float* outF[3];
    float esc[3];
    int headMode;
};

__global__ void __launch_bounds__(256) tgemm_kernel(GemmBatch gb)
{
    extern __shared__ char smc[];
    u32 sb = cvta_s(smc);

    int z = blockIdx.z;
    int tid = threadIdx.x;
    int lane = tid & 31, wid = tid >> 5;
    int g = lane >> 2, tg = lane & 3;
    int i8 = lane & 7, sel = lane >> 3;
    int m0 = blockIdx.y * 128, n0 = blockIdx.x * 128;
    int wm = (wid & 1) * 64, wn = (wid >> 1) * 32;

    const size_t K = DD;
    const bf16* pAh = gb.Ah[z] + (size_t)m0 * K;
    const bf16* pAl = gb.Al[z] + (size_t)m0 * K;
    const bf16* pBh = gb.Bh[z] + (size_t)n0 * K;
    const bf16* pBl = gb.Bl[z] + (size_t)n0 * K;

    float acc[4][4][4];
#pragma unroll
    for (int mt = 0; mt < 4; mt++)
#pragma unroll
        for (int nt = 0; nt < 4; nt++)
#pragma unroll
            for (int i = 0; i < 4; i++) acc[mt][nt][i] = 0.0f;

#pragma unroll
    for (int s = 0; s < 2; s++) {
        u32 ss = sb + (u32)(s * 65536);
        stage128(ss +     0, pAh + s * 64, 2048, tid);
        stage128(ss + 16384, pAl + s * 64, 2048, tid);
        stage128(ss + 32768, pBh + s * 64, 2048, tid);
        stage128(ss + 49152, pBl + s * 64, 2048, tid);
        cp_commit();
    }

    int buf = 0, wbuf = 2;
    for (int kt = 0; kt < 16; kt++) {
        if (kt <= 13) cp_wait1(); else cp_wait0();
        __syncthreads();
        if (kt <= 13) {
            int k1 = (kt + 2) * 64;
            u32 sn = sb + (u32)(wbuf * 65536);
            stage128(sn +     0, pAh + k1, 2048, tid);
            stage128(sn + 16384, pAl + k1, 2048, tid);
            stage128(sn + 32768, pBh + k1, 2048, tid);
            stage128(sn + 49152, pBl + k1, 2048, tid);
            cp_commit();
            wbuf = (wbuf == 2) ? 0 : wbuf + 1;
        }
        u32 st = sb + (u32)(buf * 65536);
        buf = (buf == 2) ? 0 : buf + 1;

#pragma unroll
        for (int ks4 = 0; ks4 < 4; ks4++) {
            int ks = ks4 * 16;
            u32 ah[4][4], al[4][4];
#pragma unroll
            for (int mt = 0; mt < 4; mt++) {
                int arow = wm + mt * 16 + i8 + ((sel & 1) << 3);
                u32 aoff = (u32)(arow * 128) + ((u32)((((ks >> 3) + (sel >> 1)) ^ i8)) << 4);
                ldsm_x4(ah[mt], st + aoff);
                ldsm_x4(al[mt], st + 16384 + aoff);
            }
#pragma unroll
            for (int ntp = 0; ntp < 2; ntp++) {
                int brow = wn + ntp * 16 + i8 + ((sel >> 1) << 3);
                u32 boff = (u32)(brow * 128) + ((u32)((((ks >> 3) + (sel & 1)) ^ i8)) << 4);
                u32 bh[4], bl[4];
                ldsm_x4(bh, st + 32768 + boff);
                ldsm_x4(bl, st + 49152 + boff);
#pragma unroll
                for (int mt = 0; mt < 4; mt++)
                    mma16816(acc[mt][2*ntp],   ah[mt][0], ah[mt][1], ah[mt][2], ah[mt][3], bh[0], bh[1]);
#pragma unroll
                for (int mt = 0; mt < 4; mt++)
                    mma16816(acc[mt][2*ntp+1], ah[mt][0], ah[mt][1], ah[mt][2], ah[mt][3], bh[2], bh[3]);
#pragma unroll
                for (int mt = 0; mt < 4; mt++)
                    mma16816(acc[mt][2*ntp],   ah[mt][0], ah[mt][1], ah[mt][2], ah[mt][3], bl[0], bl[1]);
#pragma unroll
                for (int mt = 0; mt < 4; mt++)
                    mma16816(acc[mt][2*ntp+1], ah[mt][0], ah[mt][1], ah[mt][2], ah[mt][3], bl[2], bl[3]);
#pragma unroll
                for (int mt = 0; mt < 4; mt++)
                    mma16816(acc[mt][2*ntp],   al[mt][0], al[mt][1], al[mt][2], al[mt][3], bh[0], bh[1]);
#pragma unroll
                for (int mt = 0; mt < 4; mt++)
                    mma16816(acc[mt][2*ntp+1], al[mt][0], al[mt][1], al[mt][2], al[mt][3], bh[2], bh[3]);
            }
        }
    }

    const float* bias = gb.bias[z];
    float escale = gb.esc[z];
#pragma unroll
    for (int mt = 0; mt < 4; mt++) {
        int r0 = m0 + wm + mt * 16 + g;
        int r1 = r0 + 8;
#pragma unroll
        for (int nt = 0; nt < 4; nt++) {
            int c = n0 + wn + nt * 8 + tg * 2;
            float b0 = bias[c], b1 = bias[c + 1];
            float v00 = (acc[mt][nt][0] + b0) * escale;
            float v01 = (acc[mt][nt][1] + b1) * escale;
            float v10 = (acc[mt][nt][2] + b0) * escale;
            float v11 = (acc[mt][nt][3] + b1) * escale;
            if (gb.headMode) {
                int h  = c >> 6;
                int dk = c & 63;
                int b_0 = r0 >> 11, s_0 = r0 & (SS - 1);
                int b_1 = r1 >> 11, s_1 = r1 & (SS - 1);
                size_t o0 = (((size_t)(b_0 * HH + h)) * SS + s_0) * DKK + dk;
                size_t o1 = (((size_t)(b_1 * HH + h)) * SS + s_1) * DKK + dk;
                bf16 h00, l00, h01, l01, h10, l10, h11, l11;
                f2bf_split(v00, h00, l00); f2bf_split(v01, h01, l01);
                f2bf_split(v10, h10, l10); f2bf_split(v11, h11, l11);
                *(u32*)&gb.oh[z][o0] = bf2_pack(h00, h01);
                *(u32*)&gb.ol[z][o0] = bf2_pack(l00, l01);
                *(u32*)&gb.oh[z][o1] = bf2_pack(h10, h11);
                *(u32*)&gb.ol[z][o1] = bf2_pack(l10, l11);
            } else {
                float2 w0; w0.x = v00; w0.y = v01;
                float2 w1; w1.x = v10; w1.y = v11;
                *(float2*)&gb.outF[z][(size_t)r0 * DD + c] = w0;
                *(float2*)&gb.outF[z][(size_t)r1 * DD + c] = w1;
            }
        }
    }
}

// ---------------------------------------------------------------------------
// Attention (two-pass, 2 CTAs/SM) — exact R12 version:
//  pass 1: 128-key chunks, K-hi only (3 x 16KB stages), lsum
//  pass 2: 64-key chunks, K+V hi/lo (2 x 32KB stages), p final, O += pV
// ---------------------------------------------------------------------------
#define ATT_SMEM (32768 + 2*32768)   // 98304 -> 2 CTAs/SM

__global__ void __launch_bounds__(256, 2) attn_kernel(
    const bf16* __restrict__ qh_hi, const bf16* __restrict__ qh_lo,
    const bf16* __restrict__ kh_hi, const bf16* __restrict__ kh_lo,
    const bf16* __restrict__ vh_hi, const bf16* __restrict__ vh_lo,
    const float* __restrict__ attn_bias, const float* __restrict__ maskbias,
    float* __restrict__ p_out,
    bf16* __restrict__ o_hi, bf16* __restrict__ o_lo)
{
    extern __shared__ char smc[];
    u32 sb = cvta_s(smc);
    u32 sQh = sb;
    u32 sQl = sb + 16384;

    int tid = threadIdx.x;
    int lane = tid & 31, wid = tid >> 5;
    int g = lane >> 2, tg = lane & 3;
    int i8 = lane & 7, sel = lane >> 3;
    int bh = blockIdx.y;
    int b  = bh >> 4;
    int q0 = blockIdx.x * 128;
    int wq = wid * 16;

    const bf16* kb_h = kh_hi + (size_t)bh * SS * DKK;
    const bf16* kb_l = kh_lo + (size_t)bh * SS * DKK;
    const bf16* vb_h = vh_hi + (size_t)bh * SS * DKK;
    const bf16* vb_l = vh_lo + (size_t)bh * SS * DKK;
    const float* mbp = maskbias + b * SS;

    // ---- Q load + pass-1 prologue (K-hi only, 3 x 16KB stages, 128-key) ----
    stage128(sQh, qh_hi + ((size_t)bh * SS + q0) * DKK, 128, tid);
    stage128(sQl, qh_lo + ((size_t)bh * SS + q0) * DKK, 128, tid);
    stage128(sb + 32768, kb_h, 128, tid);
    cp_commit();
    stage128(sb + 32768 + 16384, kb_h + (size_t)128 * DKK, 128, tid);
    cp_commit();

    float lsum0 = 0.0f, lsum1 = 0.0f;
    int rr0 = q0 + wq + g;

    // =============== PASS 1: lsum (hi-only), 16 chunks of 128 ===============
    {
        int buf = 0, wbuf = 2;
        for (int kt = 0; kt < 16; kt++) {
            if (kt <= 13) cp_wait1(); else cp_wait0();
            __syncthreads();
            if (kt <= 13) {
                int kb1 = (kt + 2) * 128;
                stage128(sb + 32768 + (u32)(wbuf * 16384),
                         kb_h + (size_t)kb1 * DKK, 128, tid);
                cp_commit();
                wbuf = (wbuf == 2) ? 0 : wbuf + 1;
            }
            u32 st = sb + 32768 + (u32)(buf * 16384);
            buf = (buf == 2) ? 0 : buf + 1;
            int kb = kt * 128;

            float sc[16][4];
#pragma unroll
            for (int nt = 0; nt < 16; nt++)
#pragma unroll
                for (int i = 0; i < 4; i++) sc[nt][i] = 0.0f;

#pragma unroll
            for (int ks4 = 0; ks4 < 4; ks4++) {
                int ks = ks4 * 16;
                int arow = wq + i8 + ((sel & 1) << 3);
                u32 aoff = (u32)(arow * 128) + ((u32)((((ks >> 3) + (sel >> 1)) ^ i8)) << 4);
                u32 qh[4];
                ldsm_x4(qh, sQh + aoff);
#pragma unroll
                for (int ntp = 0; ntp < 8; ntp++) {
                    int brow = ntp * 16 + i8 + ((sel >> 1) << 3);
                    u32 boff = (u32)(brow * 128) + ((u32)((((ks >> 3) + (sel & 1)) ^ i8)) << 4);
                    u32 bhr[4];
                    ldsm_x4(bhr, st + boff);
                    mma16816(sc[2*ntp],   qh[0], qh[1], qh[2], qh[3], bhr[0], bhr[1]);
                    mma16816(sc[2*ntp+1], qh[0], qh[1], qh[2], qh[3], bhr[2], bhr[3]);
                }
            }

#pragma unroll
            for (int nt = 0; nt < 16; nt++) {
                int j = nt * 8 + tg * 2;
                float2 mb01 = *(const float2*)(mbp + kb + j);
                lsum0 += __expf(sc[nt][0] + mb01.x);
                lsum0 += __expf(sc[nt][1] + mb01.y);
                lsum1 += __expf(sc[nt][2] + mb01.x);
                lsum1 += __expf(sc[nt][3] + mb01.y);
            }
        }
    }
    __syncthreads();

    lsum0 += __shfl_xor_sync(0xffffffffu, lsum0, 1);
    lsum0 += __shfl_xor_sync(0xffffffffu, lsum0, 2);
    lsum1 += __shfl_xor_sync(0xffffffffu, lsum1, 1);
    lsum1 += __shfl_xor_sync(0xffffffffu, lsum1, 2);
    float il0 = 1.0f / lsum0;
    float il1 = 1.0f / lsum1;

    // =============== PASS 2: p write + PV, 32 chunks of 64 ===============
    float oacc[8][4];
#pragma unroll
    for (int nt = 0; nt < 8; nt++)
#pragma unroll
        for (int i = 0; i < 4; i++) oacc[nt][i] = 0.0f;

    const float* biasrow0 = attn_bias + ((size_t)bh * SS + rr0) * SS;
    const float* biasrow1 = biasrow0 + 8 * SS;
    float* prow0 = p_out ? p_out + ((size_t)bh * SS + rr0) * SS : nullptr;
    float* prow1 = prow0 ? prow0 + 8 * SS : nullptr;

    {
        u32 s0 = sb + 32768;
        stage64(s0 +     0, kb_h, tid);
        stage64(s0 +  8192, kb_l, tid);
        stage64(s0 + 16384, vb_h, tid);
        stage64(s0 + 24576, vb_l, tid);
        cp_commit();
    }

    for (int kt = 0; kt < 32; kt++) {
        cp_wait0();
        __syncthreads();
        u32 st = sb + 32768 + (u32)((kt & 1) * 32768);
        if (kt < 31) {
            int kb1 = (kt + 1) * 64;
            u32 sn = sb + 32768 + (u32)(((kt + 1) & 1) * 32768);
            stage64(sn +     0, kb_h + (size_t)kb1 * DKK, tid);
            stage64(sn +  8192, kb_l + (size_t)kb1 * DKK, tid);
            stage64(sn + 16384, vb_h + (size_t)kb1 * DKK, tid);
            stage64(sn + 24576, vb_l + (size_t)kb1 * DKK, tid);
            cp_commit();
        }
        int kb = kt * 64;

        float sc[8][4];
#pragma unroll
        for (int nt = 0; nt < 8; nt++)
#pragma unroll
            for (int i = 0; i < 4; i++) sc[nt][i] = 0.0f;

#pragma unroll
        for (int ks4 = 0; ks4 < 4; ks4++) {
            int ks = ks4 * 16;
            int arow = wq + i8 + ((sel & 1) << 3);
            u32 aoff = (u32)(arow * 128) + ((u32)((((ks >> 3) + (sel >> 1)) ^ i8)) << 4);
            u32 qh[4], ql[4];
            ldsm_x4(qh, sQh + aoff);
            ldsm_x4(ql, sQl + aoff);
#pragma unroll
            for (int pr = 0; pr < 2; pr++) {
                int na = pr * 2, nb = pr * 2 + 1;
                int browa = na * 16 + i8 + ((sel >> 1) << 3);
                int browb = nb * 16 + i8 + ((sel >> 1) << 3);
                u32 boffa = (u32)(browa * 128) + ((u32)((((ks >> 3) + (sel & 1)) ^ i8)) << 4);
                u32 boffb = (u32)(browb * 128) + ((u32)((((ks >> 3) + (sel & 1)) ^ i8)) << 4);
                u32 bh0[4], bl0[4], bh1[4], bl1[4];
                ldsm_x4(bh0, st + boffa);
                ldsm_x4(bl0, st + 8192 + boffa);
                ldsm_x4(bh1, st + boffb);
                ldsm_x4(bl1, st + 8192 + boffb);
                mma16816(sc[2*na],   qh[0], qh[1], qh[2], qh[3], bh0[0], bh0[1]);
                mma16816(sc[2*na+1], qh[0], qh[1], qh[2], qh[3], bh0[2], bh0[3]);
                mma16816(sc[2*nb],   qh[0], qh[1], qh[2], qh[3], bh1[0], bh1[1]);
                mma16816(sc[2*nb+1], qh[0], qh[1], qh[2], qh[3], bh1[2], bh1[3]);
                mma16816(sc[2*na],   qh[0], qh[1], qh[2], qh[3], bl0[0], bl0[1]);
                mma16816(sc[2*na+1], qh[0], qh[1], qh[2], qh[3], bl0[2], bl0[3]);
                mma16816(sc[2*nb],   qh[0], qh[1], qh[2], qh[3], bl1[0], bl1[1]);
                mma16816(sc[2*nb+1], qh[0], qh[1], qh[2], qh[3], bl1[2], bl1[3]);
                mma16816(sc[2*na],   ql[0], ql[1], ql[2], ql[3], bh0[0], bh0[1]);
                mma16816(sc[2*na+1], ql[0], ql[1], ql[2], ql[3], bh0[2], bh0[3]);
                mma16816(sc[2*nb],   ql[0], ql[1], ql[2], ql[3], bh1[0], bh1[1]);
                mma16816(sc[2*nb+1], ql[0], ql[1], ql[2], ql[3], bh1[2], bh1[3]);
            }
        }

#pragma unroll
        for (int nt = 0; nt < 8; nt++) {
            int j = nt * 8 + tg * 2;
            float2 mb01 = *(const float2*)(mbp + kb + j);
            float e0 = __expf(sc[nt][0] + mb01.x) * il0;
            float e1 = __expf(sc[nt][1] + mb01.y) * il0;
            float e2 = __expf(sc[nt][2] + mb01.x) * il1;
            float e3 = __expf(sc[nt][3] + mb01.y) * il1;
            float2 bi0 = *(const float2*)(biasrow0 + kb + j);
            float2 bi1 = *(const float2*)(biasrow1 + kb + j);
            float p0 = e0 * bi0.x, p1 = e1 * bi0.y;
            float p2 = e2 * bi1.x, p3 = e3 * bi1.y;
            if (prow0) {
                float2 w0; w0.x = p0; w0.y = p1;
                float2 w1; w1.x = p2; w1.y = p3;
                *(float2*)(prow0 + kb + j) = w0;
                *(float2*)(prow1 + kb + j) = w1;
            }
            sc[nt][0] = p0; sc[nt][1] = p1; sc[nt][2] = p2; sc[nt][3] = p3;
        }

#pragma unroll
        for (int s = 0; s < 4; s++) {
            u32 pa[4], pl[4];
            split_pack2(sc[2*s    ][0], sc[2*s    ][1], pa[0], pl[0]);
            split_pack2(sc[2*s    ][2], sc[2*s    ][3], pa[1], pl[1]);
            split_pack2(sc[2*s + 1][0], sc[2*s + 1][1], pa[2], pl[2]);
            split_pack2(sc[2*s + 1][2], sc[2*s + 1][3], pa[3], pl[3]);
            int vrow = s * 16 + i8 + ((sel & 1) << 3);
#pragma unroll
            for (int pr = 0; pr < 2; pr++) {
                int na = pr * 2, nb = pr * 2 + 1;
                u32 voffa = (u32)(vrow * 128) + ((u32)(((na * 2 + (sel >> 1)) ^ i8)) << 4);
                u32 voffb = (u32)(vrow * 128) + ((u32)(((nb * 2 + (sel >> 1)) ^ i8)) << 4);
                u32 vh0[4], vl0[4], vh1[4], vl1[4];
                ldsm_x4_t(vh0, st + 16384 + voffa);
                ldsm_x4_t(vl0, st + 24576 + voffa);
                ldsm_x4_t(vh1, st + 16384 + voffb);
                ldsm_x4_t(vl1, st + 24576 + voffb);
                mma16816(oacc[2*na],   pa[0], pa[1], pa[2], pa[3], vh0[0], vh0[1]);
                mma16816(oacc[2*na+1], pa[0], pa[1], pa[2], pa[3], vh0[2], vh0[3]);
                mma16816(oacc[2*nb],   pa[0], pa[1], pa[2], pa[3], vh1[0], vh1[1]);
                mma16816(oacc[2*nb+1], pa[0], pa[1], pa[2], pa[3], vh1[2], vh1[3]);
                mma16816(oacc[2*na],   pa[0], pa[1], pa[2], pa[3], vl0[0], vl0[1]);
                mma16816(oacc[2*na+1], pa[0], pa[1], pa[2], pa[3], vl0[2], vl0[3]);
                mma16816(oacc[2*nb],   pa[0], pa[1], pa[2], pa[3], vl1[0], vl1[1]);
                mma16816(oacc[2*nb+1], pa[0], pa[1], pa[2], pa[3], vl1[2], vl1[3]);
                mma16816(oacc[2*na],   pl[0], pl[1], pl[2], pl[3], vh0[0], vh0[1]);
                mma16816(oacc[2*na+1], pl[0], pl[1], pl[2], pl[3], vh0[2], vh0[3]);
                mma16816(oacc[2*nb],   pl[0], pl[1], pl[2], pl[3], vh1[0], vh1[1]);
                mma16816(oacc[2*nb+1], pl[0], pl[1], pl[2], pl[3], vh1[2], vh1[3]);
            }
        }
    }

    // ---- O store ----
    int grow0 = b * SS + rr0;
    int grow1 = grow0 + 8;
    int hcol  = (bh & 15) * DKK;
#pragma unroll
    for (int nt = 0; nt < 8; nt++) {
        int c = hcol + nt * 8 + tg * 2;
        bf16 h00, l00, h01, l01, h10, l10, h11, l11;
        f2bf_split(oacc[nt][0], h00, l00); f2bf_split(oacc[nt][1], h01, l01);
        f2bf_split(oacc[nt][2], h10, l10); f2bf_split(oacc[nt][3], h11, l11);
        *(u32*)&o_hi[(size_t)grow0 * DD + c] = bf2_pack(h00, h01);
        *(u32*)&o_lo[(size_t)grow0 * DD + c] = bf2_pack(l00, l01);
        *(u32*)&o_hi[(size_t)grow1 * DD + c] = bf2_pack(h10, h11);
        *(u32*)&o_lo[(size_t)grow1 * DD + c] = bf2_pack(l10, l11);
    }
}

// ---------------------------------------------------------------------------
// Launch (single stream — graph-capture safe)
// ---------------------------------------------------------------------------
extern "C" void kernel_launch(void* const* d_in, const int* in_sizes, int n_in,
                              void* d_out, int out_size)
{
    const float* q    = (const float*)d_in[0];
    const float* k    = (const float*)d_in[1];
    const float* v    = (const float*)d_in[2];
    const unsigned char* mraw = (const unsigned char*)d_in[3];
    const float* bias = (const float*)d_in[4];
    const float* Wq   = (const float*)d_in[5];
    const float* bq   = (const float*)d_in[6];
    const float* Wk   = (const float*)d_in[7];
    const float* bk   = (const float*)d_in[8];
    const float* Wv   = (const float*)d_in[9];
    const float* bv   = (const float*)d_in[10];
    const float* Wo   = (const float*)d_in[11];
    const float* bo   = (const float*)d_in[12];

    float* out = (float*)d_out;
    float* p_out = ((size_t)out_size >= OUT_ELEMS + P_ELEMS) ? out + OUT_ELEMS : nullptr;

    bf16 *aq_hi, *aq_lo, *ak_hi, *ak_lo, *av_hi, *av_lo;
    bf16 *wT_hi, *wT_lo;
    bf16 *qh_hi, *qh_lo, *kh_hi, *kh_lo, *vh_hi, *vh_lo, *o_hi, *o_lo;
    float *mb;
    cudaGetSymbolAddress((void**)&aq_hi, g_aq_hi);
    cudaGetSymbolAddress((void**)&aq_lo, g_aq_lo);
    cudaGetSymbolAddress((void**)&ak_hi, g_ak_hi);
    cudaGetSymbolAddress((void**)&ak_lo, g_ak_lo);
    cudaGetSymbolAddress((void**)&av_hi, g_av_hi);
    cudaGetSymbolAddress((void**)&av_lo, g_av_lo);
    cudaGetSymbolAddress((void**)&wT_hi, g_wT_hi);
    cudaGetSymbolAddress((void**)&wT_lo, g_wT_lo);
    cudaGetSymbolAddress((void**)&qh_hi, g_qh_hi);
    cudaGetSymbolAddress((void**)&qh_lo, g_qh_lo);
    cudaGetSymbolAddress((void**)&kh_hi, g_kh_hi);
    cudaGetSymbolAddress((void**)&kh_lo, g_kh_lo);
    cudaGetSymbolAddress((void**)&vh_hi, g_vh_hi);
    cudaGetSymbolAddress((void**)&vh_lo, g_vh_lo);
    cudaGetSymbolAddress((void**)&o_hi,  g_o_hi);
    cudaGetSymbolAddress((void**)&o_lo,  g_o_lo);
    cudaGetSymbolAddress((void**)&mb,    g_mb);

    static bool attr_set = false;
    if (!attr_set) {
        cudaFuncSetAttribute(attn_kernel,
                             cudaFuncAttributeMaxDynamicSharedMemorySize, ATT_SMEM);
        cudaFuncSetAttribute(tgemm_kernel,
                             cudaFuncAttributeMaxDynamicSharedMemorySize, TG_SMEM);
        attr_set = true;
    }

    SplitBatch sbt;
    sbt.x[0] = (const float4*)q; sbt.hi[0] = (uint2*)aq_hi; sbt.lo[0] = (uint2*)aq_lo;
    sbt.x[1] = (const float4*)k; sbt.hi[1] = (uint2*)ak_hi; sbt.lo[1] = (uint2*)ak_lo;
    sbt.x[2] = (const float4*)v; sbt.hi[2] = (uint2*)av_hi; sbt.lo[2] = (uint2*)av_lo;
    sbt.mraw = mraw;
    sbt.mb = mb;
    dim3 gs(NROWS*DD/4/256, 4);   // y==3: mask plane
    split3_kernel<<<gs, 256>>>(sbt);

    SplitTBatch stb;
    stb.W[0] = Wq; stb.hiT[0] = wT_hi + 0*DD*DD; stb.loT[0] = wT_lo + 0*DD*DD;
    stb.W[1] = Wk; stb.hiT[1] = wT_hi + 1*DD*DD; stb.loT[1] = wT_lo + 1*DD*DD;
    stb.W[2] = Wv; stb.hiT[2] = wT_hi + 2*DD*DD; stb.loT[2] = wT_lo + 2*DD*DD;
    stb.W[3] = Wo; stb.hiT[3] = wT_hi + 3*DD*DD; stb.loT[3] = wT_lo + 3*DD*DD;
    dim3 gt(32, 32, 4);
    splitT4_kernel<<<gt, 256>>>(stb);

    GemmBatch gbp;
    gbp.Ah[0] = aq_hi; gbp.Al[0] = aq_lo;
    gbp.Ah[1] = ak_hi; gbp.Al[1] = ak_lo;
    gbp.Ah[2] = av_hi; gbp.Al[2] = av_lo;
    gbp.Bh[0] = wT_hi + 0*DD*DD; gbp.Bl[0] = wT_lo + 0*DD*DD;
    gbp.Bh[1] = wT_hi + 1*DD*DD; gbp.Bl[1] = wT_lo + 1*DD*DD;
    gbp.Bh[2] = wT_hi + 2*DD*DD; gbp.Bl[2] = wT_lo + 2*DD*DD;
    gbp.bias[0] = bq; gbp.bias[1] = bk; gbp.bias[2] = bv;
    gbp.oh[0] = qh_hi; gbp.ol[0] = qh_lo;
    gbp.oh[1] = kh_hi; gbp.ol[1] = kh_lo;
    gbp.oh[2] = vh_hi; gbp.ol[2] = vh_lo;
    gbp.outF[0] = gbp.outF[1] = gbp.outF[2] = nullptr;
    gbp.esc[0] = 0.125f; gbp.esc[1] = 1.0f; gbp.esc[2] = 1.0f;
    gbp.headMode = 1;
    dim3 gp3(DD / 128, NROWS / 128, 3);
    tgemm_kernel<<<gp3, 256, TG_SMEM>>>(gbp);

    dim3 ga(SS / 128, BB * HH);
    attn_kernel<<<ga, 256, ATT_SMEM>>>(qh_hi, qh_lo, kh_hi, kh_lo, vh_hi, vh_lo,
                                       bias, mb, p_out, o_hi, o_lo);

    GemmBatch gbo;
    gbo.Ah[0] = o_hi; gbo.Al[0] = o_lo;
    gbo.Bh[0] = wT_hi + 3*DD*DD; gbo.Bl[0] = wT_lo + 3*DD*DD;
    gbo.bias[0] = bo;
    gbo.oh[0] = nullptr; gbo.ol[0] = nullptr;
    gbo.outF[0] = out;
    gbo.esc[0] = 1.0f;
    gbo.headMode = 0;
    gbo.Ah[1] = gbo.Ah[2] = o_hi; gbo.Al[1] = gbo.Al[2] = o_lo;
    gbo.Bh[1] = gbo.Bh[2] = gbo.Bh[0]; gbo.Bl[1] = gbo.Bl[2] = gbo.Bl[0];
    gbo.bias[1] = gbo.bias[2] = bo;
    gbo.oh[1] = gbo.oh[2] = nullptr; gbo.ol[1] = gbo.ol[2] = nullptr;
    gbo.outF[1] = gbo.outF[2] = out;
    gbo.esc[1] = gbo.esc[2] = 1.0f;
    dim3 gp1(DD / 128, NROWS / 128, 1);
    tgemm_kernel<<<gp1, 256, TG_SMEM>>>(gbo);
}

// round 16
// speedup vs baseline: 1.0925x; 1.0254x over previous
#include <cuda_runtime.h>
#include <cuda_bf16.h>
#include <math.h>
#include <stdint.h>

typedef unsigned int u32;
typedef __nv_bfloat16 bf16;

#define BB 2
#define SS 2048
#define DD 1024
#define HH 16
#define DKK 64
#define NROWS (BB*SS)
#define OUT_ELEMS ((size_t)BB*SS*DD)
#define P_ELEMS   ((size_t)BB*HH*SS*SS)

// ---------------------------------------------------------------------------
// Device scratch (allocation-free)
// ---------------------------------------------------------------------------
__device__ __align__(16) bf16 g_aq_hi[NROWS*DD], g_aq_lo[NROWS*DD];
__device__ __align__(16) bf16 g_ak_hi[NROWS*DD], g_ak_lo[NROWS*DD];
__device__ __align__(16) bf16 g_av_hi[NROWS*DD], g_av_lo[NROWS*DD];
__device__ __align__(16) bf16 g_wT_hi[4][DD*DD], g_wT_lo[4][DD*DD];
__device__ __align__(16) bf16 g_qh_hi[NROWS*DD], g_qh_lo[NROWS*DD];
__device__ __align__(16) bf16 g_kh_hi[NROWS*DD], g_kh_lo[NROWS*DD];
__device__ __align__(16) bf16 g_vh_hi[NROWS*DD], g_vh_lo[NROWS*DD];
__device__ __align__(16) bf16 g_o_hi[NROWS*DD],  g_o_lo[NROWS*DD];
__device__ float g_mb[BB*SS];

// ---------------------------------------------------------------------------
// PTX helpers
// ---------------------------------------------------------------------------
__device__ __forceinline__ u32 cvta_s(const void* p) {
    return (u32)__cvta_generic_to_shared(p);
}
__device__ __forceinline__ void cp_async16(u32 dst, const void* src) {
    asm volatile("cp.async.cg.shared.global [%0], [%1], 16;\n" :: "r"(dst), "l"(src));
}
__device__ __forceinline__ void cp_commit() {
    asm volatile("cp.async.commit_group;\n" ::: "memory");
}
__device__ __forceinline__ void cp_wait0() {
    asm volatile("cp.async.wait_group 0;\n" ::: "memory");
}
__device__ __forceinline__ void cp_wait1() {
    asm volatile("cp.async.wait_group 1;\n" ::: "memory");
}
__device__ __forceinline__ void ldsm_x4(u32* r, u32 addr) {
    asm volatile("ldmatrix.sync.aligned.m8n8.x4.shared.b16 {%0,%1,%2,%3}, [%4];\n"
        : "=r"(r[0]), "=r"(r[1]), "=r"(r[2]), "=r"(r[3]) : "r"(addr));
}
__device__ __forceinline__ void ldsm_x4_t(u32* r, u32 addr) {
    asm volatile("ldmatrix.sync.aligned.m8n8.x4.trans.shared.b16 {%0,%1,%2,%3}, [%4];\n"
        : "=r"(r[0]), "=r"(r[1]), "=r"(r[2]), "=r"(r[3]) : "r"(addr));
}
__device__ __forceinline__ void mma16816(float* c, u32 a0, u32 a1, u32 a2, u32 a3,
                                         u32 b0, u32 b1)
{
    asm volatile(
        "mma.sync.aligned.m16n8k16.row.col.f32.bf16.bf16.f32 "
        "{%0,%1,%2,%3},{%4,%5,%6,%7},{%8,%9},{%0,%1,%2,%3};\n"
        : "+f"(c[0]), "+f"(c[1]), "+f"(c[2]), "+f"(c[3])
        : "r"(a0), "r"(a1), "r"(a2), "r"(a3), "r"(b0), "r"(b1));
}
__device__ __forceinline__ void f2bf_split(float v, bf16& h, bf16& l) {
    h = __float2bfloat16_rn(v);
    l = __float2bfloat16_rn(v - __bfloat162float(h));
}
__device__ __forceinline__ u32 bf2_pack(bf16 a, bf16 b) {
    __nv_bfloat162 t; t.x = a; t.y = b;
    return *reinterpret_cast<u32*>(&t);
}
__device__ __forceinline__ void split_pack2(float a, float b, u32& hp, u32& lp) {
    bf16 ha, la, hb, lb;
    f2bf_split(a, ha, la);
    f2bf_split(b, hb, lb);
    hp = bf2_pack(ha, hb);
    lp = bf2_pack(la, lb);
}

// Stage [128 rows x 64 bf16] into swizzled smem (128B rows, 16B chunks,
// chunk' = chunk ^ (row&7)).
__device__ __forceinline__ void stage128(u32 sbase, const bf16* g, u32 gstride_bytes, int tid) {
#pragma unroll
    for (int it = 0; it < 4; it++) {
        int idx = it * 256 + tid;
        int r = idx >> 3, c = idx & 7;
        cp_async16(sbase + (u32)(r * 128) + (u32)((c ^ (r & 7)) << 4),
                   (const char*)g + (size_t)r * gstride_bytes + (size_t)c * 16);
    }
}

// Stage [64 rows x 64 bf16] (head-major, 128B contiguous rows)
__device__ __forceinline__ void stage64(u32 sbase, const bf16* g, int tid) {
#pragma unroll
    for (int it = 0; it < 2; it++) {
        int idx = it * 256 + tid;   // 0..511
        int r = idx >> 3, c = idx & 7;
        cp_async16(sbase + (u32)(r * 128) + (u32)((c ^ (r & 7)) << 4),
                   (const char*)g + (size_t)r * 128 + (size_t)c * 16);
    }
}

// ---------------------------------------------------------------------------
// Mask conversion
// ---------------------------------------------------------------------------
__global__ void mask_kernel(const unsigned char* __restrict__ mraw, float* __restrict__ mb)
{
    __shared__ int flag1, flag3;
    int tid = threadIdx.x;
    if (tid == 0) { flag1 = 0; flag3 = 0; }
    __syncthreads();
    const int n = NROWS;
    for (int i = tid; i < n; i += blockDim.x) {
        unsigned char by = mraw[i];
        if (((i & 3) == 1) && by) flag1 = 1;
        if (((i & 3) == 3) && by) flag3 = 1;
    }
    __syncthreads();
    int mode = flag1 ? 0 : (flag3 ? 2 : 1);
    for (int i = tid; i < n; i += blockDim.x) {
        bool masked;
        if (mode == 0)      masked = (mraw[i] != 0);
        else if (mode == 1) masked = (((const int*)mraw)[i] != 0);
        else                masked = (((const float*)mraw)[i] != 0.0f);
        mb[i] = masked ? -1e30f : 0.0f;
    }
}

// ---------------------------------------------------------------------------
// Batched pre-split kernels
// ---------------------------------------------------------------------------
struct SplitBatch {
    const float4* x[3];
    uint2* hi[3];
    uint2* lo[3];
};

__global__ void __launch_bounds__(256) split3_kernel(SplitBatch sbt)
{
    int z = blockIdx.y;
    int idx = blockIdx.x * 256 + threadIdx.x;
    float4 v = sbt.x[z][idx];
    bf16 h0, l0, h1, l1, h2, l2, h3, l3;
    f2bf_split(v.x, h0, l0); f2bf_split(v.y, h1, l1);
    f2bf_split(v.z, h2, l2); f2bf_split(v.w, h3, l3);
    uint2 ho; ho.x = bf2_pack(h0, h1); ho.y = bf2_pack(h2, h3);
    uint2 lu; lu.x = bf2_pack(l0, l1); lu.y = bf2_pack(l2, l3);
    sbt.hi[z][idx] = ho;
    sbt.lo[z][idx] = lu;
}

struct SplitTBatch {
    const float* W[4];
    bf16* hiT[4];
    bf16* loT[4];
};

__global__ void __launch_bounds__(256) splitT4_kernel(SplitTBatch st)
{
    __shared__ float t[32][33];
    int z = blockIdx.z;
    const float* W = st.W[z];
    int bx = blockIdx.x * 32, by = blockIdx.y * 32;
    int tx = threadIdx.x & 31, ty = threadIdx.x >> 5;
#pragma unroll
    for (int j = 0; j < 32; j += 8)
        t[ty + j][tx] = W[(size_t)(by + ty + j) * DD + bx + tx];
    __syncthreads();
#pragma unroll
    for (int j = 0; j < 32; j += 8) {
        float v = t[tx][ty + j];
        bf16 h, l;
        f2bf_split(v, h, l);
        size_t o = (size_t)(bx + ty + j) * DD + by + tx;
        st.hiT[z][o] = h;
        st.loT[z][o] = l;
    }
}

// ---------------------------------------------------------------------------
// Batched tensor-core GEMM (bf16x3), 3-stage cp.async pipeline
// (K-tile 64, 1 CTA/SM, term-major mma issue).
// ---------------------------------------------------------------------------
#define TG_SMEM (3*65536)

struct GemmBatch {
    const bf16* Ah[3]; const bf16* Al[3];
    const bf16* Bh[3]; const bf16* Bl[3];
    const float* bias[3];
    bf16* oh[3]; bf16* ol[3];
    float* outF[3];
    float esc[3];
    int headMode;
};

__global__ void __launch_bounds__(256) tgemm_kernel(GemmBatch gb)
{
    extern __shared__ char smc[];
    u32 sb = cvta_s(smc);

    int z = blockIdx.z;
    int tid = threadIdx.x;
    int lane = tid & 31, wid = tid >> 5;
    int g = lane >> 2, tg = lane & 3;
    int i8 = lane & 7, sel = lane >> 3;
    int m0 = blockIdx.y * 128, n0 = blockIdx.x * 128;
    int wm = (wid & 1) * 64, wn = (wid >> 1) * 32;

    const size_t K = DD;
    const bf16* pAh = gb.Ah[z] + (size_t)m0 * K;
    const bf16* pAl = gb.Al[z] + (size_t)m0 * K;
    const bf16* pBh = gb.Bh[z] + (size_t)n0 * K;
    const bf16* pBl = gb.Bl[z] + (size_t)n0 * K;

    float acc[4][4][4];
#pragma unroll
    for (int mt = 0; mt < 4; mt++)
#pragma unroll
        for (int nt = 0; nt < 4; nt++)
#pragma unroll
            for (int i = 0; i < 4; i++) acc[mt][nt][i] = 0.0f;

#pragma unroll
    for (int s = 0; s < 2; s++) {
        u32 ss = sb + (u32)(s * 65536);
        stage128(ss +     0, pAh + s * 64, 2048, tid);
        stage128(ss + 16384, pAl + s * 64, 2048, tid);
        stage128(ss + 32768, pBh + s * 64, 2048, tid);
        stage128(ss + 49152, pBl + s * 64, 2048, tid);
        cp_commit();
    }

    int buf = 0, wbuf = 2;
    for (int kt = 0; kt < 16; kt++) {
        if (kt <= 13) cp_wait1(); else cp_wait0();
        __syncthreads();
        if (kt <= 13) {
            int k1 = (kt + 2) * 64;
            u32 sn = sb + (u32)(wbuf * 65536);
            stage128(sn +     0, pAh + k1, 2048, tid);
            stage128(sn + 16384, pAl + k1, 2048, tid);
            stage128(sn + 32768, pBh + k1, 2048, tid);
            stage128(sn + 49152, pBl + k1, 2048, tid);
            cp_commit();
            wbuf = (wbuf == 2) ? 0 : wbuf + 1;
        }
        u32 st = sb + (u32)(buf * 65536);
        buf = (buf == 2) ? 0 : buf + 1;

#pragma unroll
        for (int ks4 = 0; ks4 < 4; ks4++) {
            int ks = ks4 * 16;
            u32 ah[4][4], al[4][4];
#pragma unroll
            for (int mt = 0; mt < 4; mt++) {
                int arow = wm + mt * 16 + i8 + ((sel & 1) << 3);
                u32 aoff = (u32)(arow * 128) + ((u32)((((ks >> 3) + (sel >> 1)) ^ i8)) << 4);
                ldsm_x4(ah[mt], st + aoff);
                ldsm_x4(al[mt], st + 16384 + aoff);
            }
#pragma unroll
            for (int ntp = 0; ntp < 2; ntp++) {
                int brow = wn + ntp * 16 + i8 + ((sel >> 1) << 3);
                u32 boff = (u32)(brow * 128) + ((u32)((((ks >> 3) + (sel & 1)) ^ i8)) << 4);
                u32 bh[4], bl[4];
                ldsm_x4(bh, st + 32768 + boff);
                ldsm_x4(bl, st + 49152 + boff);
#pragma unroll
                for (int mt = 0; mt < 4; mt++)
                    mma16816(acc[mt][2*ntp],   ah[mt][0], ah[mt][1], ah[mt][2], ah[mt][3], bh[0], bh[1]);
#pragma unroll
                for (int mt = 0; mt < 4; mt++)
                    mma16816(acc[mt][2*ntp+1], ah[mt][0], ah[mt][1], ah[mt][2], ah[mt][3], bh[2], bh[3]);
#pragma unroll
                for (int mt = 0; mt < 4; mt++)
                    mma16816(acc[mt][2*ntp],   ah[mt][0], ah[mt][1], ah[mt][2], ah[mt][3], bl[0], bl[1]);
#pragma unroll
                for (int mt = 0; mt < 4; mt++)
                    mma16816(acc[mt][2*ntp+1], ah[mt][0], ah[mt][1], ah[mt][2], ah[mt][3], bl[2], bl[3]);
#pragma unroll
                for (int mt = 0; mt < 4; mt++)
                    mma16816(acc[mt][2*ntp],   al[mt][0], al[mt][1], al[mt][2], al[mt][3], bh[0], bh[1]);
#pragma unroll
                for (int mt = 0; mt < 4; mt++)
                    mma16816(acc[mt][2*ntp+1], al[mt][0], al[mt][1], al[mt][2], al[mt][3], bh[2], bh[3]);
            }
        }
    }

    const float* bias = gb.bias[z];
    float escale = gb.esc[z];
#pragma unroll
    for (int mt = 0; mt < 4; mt++) {
        int r0 = m0 + wm + mt * 16 + g;
        int r1 = r0 + 8;
#pragma unroll
        for (int nt = 0; nt < 4; nt++) {
            int c = n0 + wn + nt * 8 + tg * 2;
            float b0 = bias[c], b1 = bias[c + 1];
            float v00 = (acc[mt][nt][0] + b0) * escale;
            float v01 = (acc[mt][nt][1] + b1) * escale;
            float v10 = (acc[mt][nt][2] + b0) * escale;
            float v11 = (acc[mt][nt][3] + b1) * escale;
            if (gb.headMode) {
                int h  = c >> 6;
                int dk = c & 63;
                int b_0 = r0 >> 11, s_0 = r0 & (SS - 1);
                int b_1 = r1 >> 11, s_1 = r1 & (SS - 1);
                size_t o0 = (((size_t)(b_0 * HH + h)) * SS + s_0) * DKK + dk;
                size_t o1 = (((size_t)(b_1 * HH + h)) * SS + s_1) * DKK + dk;
                bf16 h00, l00, h01, l01, h10, l10, h11, l11;
                f2bf_split(v00, h00, l00); f2bf_split(v01, h01, l01);
                f2bf_split(v10, h10, l10); f2bf_split(v11, h11, l11);
                *(u32*)&gb.oh[z][o0] = bf2_pack(h00, h01);
                *(u32*)&gb.ol[z][o0] = bf2_pack(l00, l01);
                *(u32*)&gb.oh[z][o1] = bf2_pack(h10, h11);
                *(u32*)&gb.ol[z][o1] = bf2_pack(l10, l11);
            } else {
                float2 w0; w0.x = v00; w0.y = v01;
                float2 w1; w1.x = v10; w1.y = v11;
                *(float2*)&gb.outF[z][(size_t)r0 * DD + c] = w0;
                *(float2*)&gb.outF[z][(size_t)r1 * DD + c] = w1;
            }
        }
    }
}

// ---------------------------------------------------------------------------
// Attention (two-pass, 2 CTAs/SM):
//  pass 1: 128-key chunks, K-hi only (3 x 16KB stages), lsum
//  pass 2: 64-key chunks, K+V hi/lo (2 x 32KB stages), p final, O += pV
// smem: Qh 0 | Ql 16384 | stages at 32768 (64KB region shared by both passes)
// ---------------------------------------------------------------------------
#define ATT_SMEM (32768 + 2*32768)   // 98304 -> 2 CTAs/SM

__global__ void __launch_bounds__(256, 2) attn_kernel(
    const bf16* __restrict__ qh_hi, const bf16* __restrict__ qh_lo,
    const bf16* __restrict__ kh_hi, const bf16* __restrict__ kh_lo,
    const bf16* __restrict__ vh_hi, const bf16* __restrict__ vh_lo,
    const float* __restrict__ attn_bias, const float* __restrict__ maskbias,
    float* __restrict__ p_out,
    bf16* __restrict__ o_hi, bf16* __restrict__ o_lo)
{
    extern __shared__ char smc[];
    u32 sb = cvta_s(smc);
    u32 sQh = sb;
    u32 sQl = sb + 16384;

    int tid = threadIdx.x;
    int lane = tid & 31, wid = tid >> 5;
    int g = lane >> 2, tg = lane & 3;
    int i8 = lane & 7, sel = lane >> 3;
    int bh = blockIdx.y;
    int b  = bh >> 4;
    int q0 = blockIdx.x * 128;
    int wq = wid * 16;

    const bf16* kb_h = kh_hi + (size_t)bh * SS * DKK;
    const bf16* kb_l = kh_lo + (size_t)bh * SS * DKK;
    const bf16* vb_h = vh_hi + (size_t)bh * SS * DKK;
    const bf16* vb_l = vh_lo + (size_t)bh * SS * DKK;
    const float* mbp = maskbias + b * SS;

    // ---- Q load + pass-1 prologue (K-hi only, 3 x 16KB stages, 128-key) ----
    stage128(sQh, qh_hi + ((size_t)bh * SS + q0) * DKK, 128, tid);
    stage128(sQl, qh_lo + ((size_t)bh * SS + q0) * DKK, 128, tid);
    stage128(sb + 32768, kb_h, 128, tid);
    cp_commit();
    stage128(sb + 32768 + 16384, kb_h + (size_t)128 * DKK, 128, tid);
    cp_commit();

    float lsum0 = 0.0f, lsum1 = 0.0f;
    int rr0 = q0 + wq + g;

    // =============== PASS 1: lsum (hi-only), 16 chunks of 128 ===============
    {
        int buf = 0, wbuf = 2;
        for (int kt = 0; kt < 16; kt++) {
            if (kt <= 13) cp_wait1(); else cp_wait0();
            __syncthreads();
            if (kt <= 13) {
                int kb1 = (kt + 2) * 128;
                stage128(sb + 32768 + (u32)(wbuf * 16384),
                         kb_h + (size_t)kb1 * DKK, 128, tid);
                cp_commit();
                wbuf = (wbuf == 2) ? 0 : wbuf + 1;
            }
            u32 st = sb + 32768 + (u32)(buf * 16384);
            buf = (buf == 2) ? 0 : buf + 1;
            int kb = kt * 128;

            float sc[16][4];
#pragma unroll
            for (int nt = 0; nt < 16; nt++)
#pragma unroll
                for (int i = 0; i < 4; i++) sc[nt][i] = 0.0f;

#pragma unroll
            for (int ks4 = 0; ks4 < 4; ks4++) {
                int ks = ks4 * 16;
                int arow = wq + i8 + ((sel & 1) << 3);
                u32 aoff = (u32)(arow * 128) + ((u32)((((ks >> 3) + (sel >> 1)) ^ i8)) << 4);
                u32 qh[4];
                ldsm_x4(qh, sQh + aoff);
#pragma unroll
                for (int ntp = 0; ntp < 8; ntp++) {
                    int brow = ntp * 16 + i8 + ((sel >> 1) << 3);
                    u32 boff = (u32)(brow * 128) + ((u32)((((ks >> 3) + (sel & 1)) ^ i8)) << 4);
                    u32 bhr[4];
                    ldsm_x4(bhr, st + boff);
                    mma16816(sc[2*ntp],   qh[0], qh[1], qh[2], qh[3], bhr[0], bhr[1]);
                    mma16816(sc[2*ntp+1], qh[0], qh[1], qh[2], qh[3], bhr[2], bhr[3]);
                }
            }

#pragma unroll
            for (int nt = 0; nt < 16; nt++) {
                int j = nt * 8 + tg * 2;
                float2 mb01 = *(const float2*)(mbp + kb + j);
                lsum0 += __expf(sc[nt][0] + mb01.x);
                lsum0 += __expf(sc[nt][1] + mb01.y);
                lsum1 += __expf(sc[nt][2] + mb01.x);
                lsum1 += __expf(sc[nt][3] + mb01.y);
            }
        }
    }
    __syncthreads();

    lsum0 += __shfl_xor_sync(0xffffffffu, lsum0, 1);
    lsum0 += __shfl_xor_sync(0xffffffffu, lsum0, 2);
    lsum1 += __shfl_xor_sync(0xffffffffu, lsum1, 1);
    lsum1 += __shfl_xor_sync(0xffffffffu, lsum1, 2);
    float il0 = 1.0f / lsum0;
    float il1 = 1.0f / lsum1;

    // =============== PASS 2: p write + PV, 32 chunks of 64 ===============
    float oacc[8][4];
#pragma unroll
    for (int nt = 0; nt < 8; nt++)
#pragma unroll
        for (int i = 0; i < 4; i++) oacc[nt][i] = 0.0f;

    const float* biasrow0 = attn_bias + ((size_t)bh * SS + rr0) * SS;
    const float* biasrow1 = biasrow0 + 8 * SS;
    float* prow0 = p_out ? p_out + ((size_t)bh * SS + rr0) * SS : nullptr;
    float* prow1 = prow0 ? prow0 + 8 * SS : nullptr;

    // pass-2 stage layout (32KB): Kh +0, Kl +8192, Vh +16384, Vl +24576
    {
        u32 s0 = sb + 32768;
        stage64(s0 +     0, kb_h, tid);
        stage64(s0 +  8192, kb_l, tid);
        stage64(s0 + 16384, vb_h, tid);
        stage64(s0 + 24576, vb_l, tid);
        cp_commit();
    }

    for (int kt = 0; kt < 32; kt++) {
        cp_wait0();
        __syncthreads();
        u32 st = sb + 32768 + (u32)((kt & 1) * 32768);
        if (kt < 31) {
            int kb1 = (kt + 1) * 64;
            u32 sn = sb + 32768 + (u32)(((kt + 1) & 1) * 32768);
            stage64(sn +     0, kb_h + (size_t)kb1 * DKK, tid);
            stage64(sn +  8192, kb_l + (size_t)kb1 * DKK, tid);
            stage64(sn + 16384, vb_h + (size_t)kb1 * DKK, tid);
            stage64(sn + 24576, vb_l + (size_t)kb1 * DKK, tid);
            cp_commit();
        }
        int kb = kt * 64;

        // ---- QK^T (bf16x3), ntp pairs interleaved ----
        float sc[8][4];
#pragma unroll
        for (int nt = 0; nt < 8; nt++)
#pragma unroll
            for (int i = 0; i < 4; i++) sc[nt][i] = 0.0f;

#pragma unroll
        for (int ks4 = 0; ks4 < 4; ks4++) {
            int ks = ks4 * 16;
            int arow = wq + i8 + ((sel & 1) << 3);
            u32 aoff = (u32)(arow * 128) + ((u32)((((ks >> 3) + (sel >> 1)) ^ i8)) << 4);
            u32 qh[4], ql[4];
            ldsm_x4(qh, sQh + aoff);
            ldsm_x4(ql, sQl + aoff);
#pragma unroll
            for (int pr = 0; pr < 2; pr++) {
                int na = pr * 2, nb = pr * 2 + 1;
                int browa = na * 16 + i8 + ((sel >> 1) << 3);
                int browb = nb * 16 + i8 + ((sel >> 1) << 3);
                u32 boffa = (u32)(browa * 128) + ((u32)((((ks >> 3) + (sel & 1)) ^ i8)) << 4);
                u32 boffb = (u32)(browb * 128) + ((u32)((((ks >> 3) + (sel & 1)) ^ i8)) << 4);
                u32 bh0[4], bl0[4], bh1[4], bl1[4];
                ldsm_x4(bh0, st + boffa);
                ldsm_x4(bl0, st + 8192 + boffa);
                ldsm_x4(bh1, st + boffb);
                ldsm_x4(bl1, st + 8192 + boffb);
                mma16816(sc[2*na],   qh[0], qh[1], qh[2], qh[3], bh0[0], bh0[1]);
                mma16816(sc[2*na+1], qh[0], qh[1], qh[2], qh[3], bh0[2], bh0[3]);
                mma16816(sc[2*nb],   qh[0], qh[1], qh[2], qh[3], bh1[0], bh1[1]);
                mma16816(sc[2*nb+1], qh[0], qh[1], qh[2], qh[3], bh1[2], bh1[3]);
                mma16816(sc[2*na],   qh[0], qh[1], qh[2], qh[3], bl0[0], bl0[1]);
                mma16816(sc[2*na+1], qh[0], qh[1], qh[2], qh[3], bl0[2], bl0[3]);
                mma16816(sc[2*nb],   qh[0], qh[1], qh[2], qh[3], bl1[0], bl1[1]);
                mma16816(sc[2*nb+1], qh[0], qh[1], qh[2], qh[3], bl1[2], bl1[3]);
                mma16816(sc[2*na],   ql[0], ql[1], ql[2], ql[3], bh0[0], bh0[1]);
                mma16816(sc[2*na+1], ql[0], ql[1], ql[2], ql[3], bh0[2], bh0[3]);
                mma16816(sc[2*nb],   ql[0], ql[1], ql[2], ql[3], bh1[0], bh1[1]);
                mma16816(sc[2*nb+1], ql[0], ql[1], ql[2], ql[3], bh1[2], bh1[3]);
            }
        }

        // ---- p = exp(s+mb) * il * bias, write FINAL p ----
#pragma unroll
        for (int nt = 0; nt < 8; nt++) {
            int j = nt * 8 + tg * 2;
            float2 mb01 = *(const float2*)(mbp + kb + j);
            float e0 = __expf(sc[nt][0] + mb01.x) * il0;
            float e1 = __expf(sc[nt][1] + mb01.y) * il0;
            float e2 = __expf(sc[nt][2] + mb01.x) * il1;
            float e3 = __expf(sc[nt][3] + mb01.y) * il1;
            float2 bi0 = *(const float2*)(biasrow0 + kb + j);
            float2 bi1 = *(const float2*)(biasrow1 + kb + j);
            float p0 = e0 * bi0.x, p1 = e1 * bi0.y;
            float p2 = e2 * bi1.x, p3 = e3 * bi1.y;
            if (prow0) {
                float2 w0; w0.x = p0; w0.y = p1;
                float2 w1; w1.x = p2; w1.y = p3;
                *(float2*)(prow0 + kb + j) = w0;
                *(float2*)(prow1 + kb + j) = w1;
            }
            sc[nt][0] = p0; sc[nt][1] = p1; sc[nt][2] = p2; sc[nt][3] = p3;
        }

        // ---- PV with final p, ntp pairs interleaved ----
#pragma unroll
        for (int s = 0; s < 4; s++) {
            u32 pa[4], pl[4];
            split_pack2(sc[2*s    ][0], sc[2*s    ][1], pa[0], pl[0]);
            split_pack2(sc[2*s    ][2], sc[2*s    ][3], pa[1], pl[1]);
            split_pack2(sc[2*s + 1][0], sc[2*s + 1][1], pa[2], pl[2]);
            split_pack2(sc[2*s + 1][2], sc[2*s + 1][3], pa[3], pl[3]);
            int vrow = s * 16 + i8 + ((sel & 1) << 3);
#pragma unroll
            for (int pr = 0; pr < 2; pr++) {
                int na = pr * 2, nb = pr * 2 + 1;
                u32 voffa = (u32)(vrow * 128) + ((u32)(((na * 2 + (sel >> 1)) ^ i8)) << 4);
                u32 voffb = (u32)(vrow * 128) + ((u32)(((nb * 2 + (sel >> 1)) ^ i8)) << 4);
                u32 vh0[4], vl0[4], vh1[4], vl1[4];
                ldsm_x4_t(vh0, st + 16384 + voffa);
                ldsm_x4_t(vl0, st + 24576 + voffa);
                ldsm_x4_t(vh1, st + 16384 + voffb);
                ldsm_x4_t(vl1, st + 24576 + voffb);
                mma16816(oacc[2*na],   pa[0], pa[1], pa[2], pa[3], vh0[0], vh0[1]);
                mma16816(oacc[2*na+1], pa[0], pa[1], pa[2], pa[3], vh0[2], vh0[3]);
                mma16816(oacc[2*nb],   pa[0], pa[1], pa[2], pa[3], vh1[0], vh1[1]);
                mma16816(oacc[2*nb+1], pa[0], pa[1], pa[2], pa[3], vh1[2], vh1[3]);
                mma16816(oacc[2*na],   pa[0], pa[1], pa[2], pa[3], vl0[0], vl0[1]);
                mma16816(oacc[2*na+1], pa[0], pa[1], pa[2], pa[3], vl0[2], vl0[3]);
                mma16816(oacc[2*nb],   pa[0], pa[1], pa[2], pa[3], vl1[0], vl1[1]);
                mma16816(oacc[2*nb+1], pa[0], pa[1], pa[2], pa[3], vl1[2], vl1[3]);
                mma16816(oacc[2*na],   pl[0], pl[1], pl[2], pl[3], vh0[0], vh0[1]);
                mma16816(oacc[2*na+1], pl[0], pl[1], pl[2], pl[3], vh0[2], vh0[3]);
                mma16816(oacc[2*nb],   pl[0], pl[1], pl[2], pl[3], vh1[0], vh1[1]);
                mma16816(oacc[2*nb+1], pl[0], pl[1], pl[2], pl[3], vh1[2], vh1[3]);
            }
        }
    }

    // ---- O store ----
    int grow0 = b * SS + rr0;
    int grow1 = grow0 + 8;
    int hcol  = (bh & 15) * DKK;
#pragma unroll
    for (int nt = 0; nt < 8; nt++) {
        int c = hcol + nt * 8 + tg * 2;
        bf16 h00, l00, h01, l01, h10, l10, h11, l11;
        f2bf_split(oacc[nt][0], h00, l00); f2bf_split(oacc[nt][1], h01, l01);
        f2bf_split(oacc[nt][2], h10, l10); f2bf_split(oacc[nt][3], h11, l11);
        *(u32*)&o_hi[(size_t)grow0 * DD + c] = bf2_pack(h00, h01);
        *(u32*)&o_lo[(size_t)grow0 * DD + c] = bf2_pack(l00, l01);
        *(u32*)&o_hi[(size_t)grow1 * DD + c] = bf2_pack(h10, h11);
        *(u32*)&o_lo[(size_t)grow1 * DD + c] = bf2_pack(l10, l11);
    }
}

// ---------------------------------------------------------------------------
// Launch (single stream — graph-capture safe)
// ---------------------------------------------------------------------------
extern "C" void kernel_launch(void* const* d_in, const int* in_sizes, int n_in,
                              void* d_out, int out_size)
{
    const float* q    = (const float*)d_in[0];
    const float* k    = (const float*)d_in[1];
    const float* v    = (const float*)d_in[2];
    const unsigned char* mraw = (const unsigned char*)d_in[3];
    const float* bias = (const float*)d_in[4];
    const float* Wq   = (const float*)d_in[5];
    const float* bq   = (const float*)d_in[6];
    const float* Wk   = (const float*)d_in[7];
    const float* bk   = (const float*)d_in[8];
    const float* Wv   = (const float*)d_in[9];
    const float* bv   = (const float*)d_in[10];
    const float* Wo   = (const float*)d_in[11];
    const float* bo   = (const float*)d_in[12];

    float* out = (float*)d_out;
    float* p_out = ((size_t)out_size >= OUT_ELEMS + P_ELEMS) ? out + OUT_ELEMS : nullptr;

    bf16 *aq_hi, *aq_lo, *ak_hi, *ak_lo, *av_hi, *av_lo;
    bf16 *wT_hi, *wT_lo;
    bf16 *qh_hi, *qh_lo, *kh_hi, *kh_lo, *vh_hi, *vh_lo, *o_hi, *o_lo;
    float *mb;
    cudaGetSymbolAddress((void**)&aq_hi, g_aq_hi);
    cudaGetSymbolAddress((void**)&aq_lo, g_aq_lo);
    cudaGetSymbolAddress((void**)&ak_hi, g_ak_hi);
    cudaGetSymbolAddress((void**)&ak_lo, g_ak_lo);
    cudaGetSymbolAddress((void**)&av_hi, g_av_hi);
    cudaGetSymbolAddress((void**)&av_lo, g_av_lo);
    cudaGetSymbolAddress((void**)&wT_hi, g_wT_hi);
    cudaGetSymbolAddress((void**)&wT_lo, g_wT_lo);
    cudaGetSymbolAddress((void**)&qh_hi, g_qh_hi);
    cudaGetSymbolAddress((void**)&qh_lo, g_qh_lo);
    cudaGetSymbolAddress((void**)&kh_hi, g_kh_hi);
    cudaGetSymbolAddress((void**)&kh_lo, g_kh_lo);
    cudaGetSymbolAddress((void**)&vh_hi, g_vh_hi);
    cudaGetSymbolAddress((void**)&vh_lo, g_vh_lo);
    cudaGetSymbolAddress((void**)&o_hi,  g_o_hi);
    cudaGetSymbolAddress((void**)&o_lo,  g_o_lo);
    cudaGetSymbolAddress((void**)&mb,    g_mb);

    static bool attr_set = false;
    if (!attr_set) {
        cudaFuncSetAttribute(attn_kernel,
                             cudaFuncAttributeMaxDynamicSharedMemorySize, ATT_SMEM);
        cudaFuncSetAttribute(tgemm_kernel,
                             cudaFuncAttributeMaxDynamicSharedMemorySize, TG_SMEM);
        attr_set = true;
    }

    mask_kernel<<<1, 1024>>>(mraw, mb);

    SplitBatch sbt;
    sbt.x[0] = (const float4*)q; sbt.hi[0] = (uint2*)aq_hi; sbt.lo[0] = (uint2*)aq_lo;
    sbt.x[1] = (const float4*)k; sbt.hi[1] = (uint2*)ak_hi; sbt.lo[1] = (uint2*)ak_lo;
    sbt.x[2] = (const float4*)v; sbt.hi[2] = (uint2*)av_hi; sbt.lo[2] = (uint2*)av_lo;
    dim3 gs(NROWS*DD/4/256, 3);
    split3_kernel<<<gs, 256>>>(sbt);

    SplitTBatch stb;
    stb.W[0] = Wq; stb.hiT[0] = wT_hi + 0*DD*DD; stb.loT[0] = wT_lo + 0*DD*DD;
    stb.W[1] = Wk; stb.hiT[1] = wT_hi + 1*DD*DD; stb.loT[1] = wT_lo + 1*DD*DD;
    stb.W[2] = Wv; stb.hiT[2] = wT_hi + 2*DD*DD; stb.loT[2] = wT_lo + 2*DD*DD;
    stb.W[3] = Wo; stb.hiT[3] = wT_hi + 3*DD*DD; stb.loT[3] = wT_lo + 3*DD*DD;
    dim3 gt(32, 32, 4);
    splitT4_kernel<<<gt, 256>>>(stb);

    GemmBatch gbp;
    gbp.Ah[0] = aq_hi; gbp.Al[0] = aq_lo;
    gbp.Ah[1] = ak_hi; gbp.Al[1] = ak_lo;
    gbp.Ah[2] = av_hi; gbp.Al[2] = av_lo;
    gbp.Bh[0] = wT_hi + 0*DD*DD; gbp.Bl[0] = wT_lo + 0*DD*DD;
    gbp.Bh[1] = wT_hi + 1*DD*DD; gbp.Bl[1] = wT_lo + 1*DD*DD;
    gbp.Bh[2] = wT_hi + 2*DD*DD; gbp.Bl[2] = wT_lo + 2*DD*DD;
    gbp.bias[0] = bq; gbp.bias[1] = bk; gbp.bias[2] = bv;
    gbp.oh[0] = qh_hi; gbp.ol[0] = qh_lo;
    gbp.oh[1] = kh_hi; gbp.ol[1] = kh_lo;
    gbp.oh[2] = vh_hi; gbp.ol[2] = vh_lo;
    gbp.outF[0] = gbp.outF[1] = gbp.outF[2] = nullptr;
    gbp.esc[0] = 0.125f; gbp.esc[1] = 1.0f; gbp.esc[2] = 1.0f;
    gbp.headMode = 1;
    dim3 gp3(DD / 128, NROWS / 128, 3);
    tgemm_kernel<<<gp3, 256, TG_SMEM>>>(gbp);

    dim3 ga(SS / 128, BB * HH);
    attn_kernel<<<ga, 256, ATT_SMEM>>>(qh_hi, qh_lo, kh_hi, kh_lo, vh_hi, vh_lo,
                                       bias, mb, p_out, o_hi, o_lo);

    GemmBatch gbo;
    gbo.Ah[0] = o_hi; gbo.Al[0] = o_lo;
    gbo.Bh[0] = wT_hi + 3*DD*DD; gbo.Bl[0] = wT_lo + 3*DD*DD;
    gbo.bias[0] = bo;
    gbo.oh[0] = nullptr; gbo.ol[0] = nullptr;
    gbo.outF[0] = out;
    gbo.esc[0] = 1.0f;
    gbo.headMode = 0;
    gbo.Ah[1] = gbo.Ah[2] = o_hi; gbo.Al[1] = gbo.Al[2] = o_lo;
    gbo.Bh[1] = gbo.Bh[2] = gbo.Bh[0]; gbo.Bl[1] = gbo.Bl[2] = gbo.Bl[0];
    gbo.bias[1] = gbo.bias[2] = bo;
    gbo.oh[1] = gbo.oh[2] = nullptr; gbo.ol[1] = gbo.ol[2] = nullptr;
    gbo.outF[1] = gbo.outF[2] = out;
    gbo.esc[1] = gbo.esc[2] = 1.0f;
    dim3 gp1(DD / 128, NROWS / 128, 1);
    tgemm_kernel<<<gp1, 256, TG_SMEM>>>(gbo);
}